// round 9
// baseline (speedup 1.0000x reference)
#include <cuda_runtime.h>
#include <cuda_fp16.h>
#include <cstdint>

#define HID 512
#define BATCH 512
#define G4 2048
#define NCH0 9
#define NCH1 16
#define KTOT0 576
#define KTOT1 1024
#define SEQ 128
#define FUT 48
#define TF_DIM 24
#define OUT_DIM 8
#define NCTA 128

#define THREADS 512
#define A_TILE_B 8192
#define B_TILE_B 16384
#define STAGE_B (A_TILE_B + B_TILE_B)     // 24576
#define W0_B (NCH0 * B_TILE_B)            // 147456
#define RING_OFF W0_B
#define MBAR_OFF (W0_B + 3 * STAGE_B)     // 221184
#define SMEM_TOT (MBAR_OFF + 64)          // 221248
#define C0A_OFF (RING_OFF + 2 * STAGE_B + A_TILE_B)  // stage-2 B-half (free in l0)
#define CHSLAB 65536                      // bytes per (chunk, full-batch) A slab

// ---------------- persistent device buffers (chunk-tiled, pre-swizzled) ----------
__device__ __align__(256) __half g_w0[16 * NCH0 * 128 * 64];
__device__ __align__(256) __half g_w1[16 * NCH1 * 128 * 64];
__device__ __align__(256) __half g_xp[SEQ * BATCH * 64];
__device__ __align__(256) __half g_h0[2][BATCH * HID];
__device__ __align__(256) __half g_h1[2][BATCH * HID];
__device__ __align__(256) float g_h1f[BATCH * HID];
__device__ __align__(256) float g_c0[BATCH * HID];
__device__ __align__(256) float g_c1[BATCH * HID];
__device__ __align__(256) float g_b0[G4];
__device__ __align__(256) float g_b1[G4];
__device__ unsigned g_barcnt = 0;
__device__ volatile unsigned g_bargen = 0;

// ---------------- helpers ----------------
__device__ __forceinline__ int swz(int k, int r) {
    return (((k >> 3) ^ (r & 7)) << 3) | (k & 7);
}
__device__ __forceinline__ uint32_t smem_u32(const void* p) {
    uint32_t a;
    asm("{ .reg .u64 t; cvta.to.shared.u64 t, %1; cvt.u32.u64 %0, t; }" : "=r"(a) : "l"(p));
    return a;
}
__device__ __forceinline__ void cpbulk(uint32_t dst, const void* src, uint32_t bytes,
                                       uint32_t mbar) {
    asm volatile(
        "cp.async.bulk.shared::cluster.global.mbarrier::complete_tx::bytes "
        "[%0], [%1], %2, [%3];"
        :: "r"(dst), "l"(src), "r"(bytes), "r"(mbar) : "memory");
}
#define FENCE_ASYNC() asm volatile("fence.proxy.async.shared::cta;" ::: "memory")
#define MBAR_INIT(a, n) asm volatile("mbarrier.init.shared.b64 [%0], %1;" :: "r"(a), "r"(n) : "memory")
#define MBAR_EXPECT_TX(a, tx) asm volatile("mbarrier.arrive.expect_tx.shared.b64 _, [%0], %1;" :: "r"(a), "r"(tx) : "memory")

__device__ __forceinline__ void mbar_wait(uint32_t mbar, uint32_t parity) {
    asm volatile(
        "{\n\t.reg .pred P1;\n\t"
        "WL_%=:\n\t"
        "mbarrier.try_wait.parity.acquire.cta.shared::cta.b64 P1, [%0], %1, 0x989680;\n\t"
        "@P1 bra.uni WD_%=;\n\t"
        "bra.uni WL_%=;\n\t"
        "WD_%=:\n\t}"
        :: "r"(mbar), "r"(parity) : "memory");
}
__device__ __forceinline__ void ldsm4(uint32_t* r, uint32_t addr) {
    asm volatile("ldmatrix.sync.aligned.m8n8.x4.shared.b16 {%0,%1,%2,%3}, [%4];"
                 : "=r"(r[0]), "=r"(r[1]), "=r"(r[2]), "=r"(r[3]) : "r"(addr));
}
__device__ __forceinline__ void mma16816(float* c, const uint32_t* a, const uint32_t* b) {
    asm volatile(
        "mma.sync.aligned.m16n8k16.row.col.f32.f16.f16.f32 "
        "{%0,%1,%2,%3}, {%4,%5,%6,%7}, {%8,%9}, {%0,%1,%2,%3};"
        : "+f"(c[0]), "+f"(c[1]), "+f"(c[2]), "+f"(c[3])
        : "r"(a[0]), "r"(a[1]), "r"(a[2]), "r"(a[3]), "r"(b[0]), "r"(b[1]));
}
__device__ __forceinline__ float sigf(float x) { return 1.0f / (1.0f + __expf(-x)); }

__device__ __forceinline__ void gridbar() {
    __syncthreads();
    if (threadIdx.x == 0) {
        __threadfence();
        unsigned gen = g_bargen;
        if (atomicAdd(&g_barcnt, 1) == NCTA - 1) {
            g_barcnt = 0;
            __threadfence();
            g_bargen = gen + 1;
        } else {
            while (g_bargen == gen) __nanosleep(64);
        }
    }
    __syncthreads();
}

// ---------------- prep kernels ----------------
__global__ void prep_w0(const float* __restrict__ wih, const float* __restrict__ whh) {
    int idx = blockIdx.x * blockDim.x + threadIdx.x;
    if (idx >= G4 * KTOT0) return;
    int n = idx / KTOT0, k = idx - n * KTOT0;
    int row = (n & 3) * HID + (n >> 2);
    float v;
    if (k < 64) v = (k < 32) ? wih[row * 32 + k] : 0.0f;
    else        v = whh[row * HID + (k - 64)];
    int r = n & 127;
    size_t dst = ((size_t)((n >> 7) * NCH0 + (k >> 6)) * 128 + r) * 64 + swz(k & 63, r);
    g_w0[dst] = __float2half(v);
}
__global__ void prep_w1(const float* __restrict__ wih, const float* __restrict__ whh) {
    int idx = blockIdx.x * blockDim.x + threadIdx.x;
    if (idx >= G4 * KTOT1) return;
    int n = idx >> 10, k = idx & 1023;
    int row = (n & 3) * HID + (n >> 2);
    float v = (k < HID) ? wih[row * HID + k] : whh[row * HID + (k - HID)];
    int r = n & 127;
    size_t dst = ((size_t)((n >> 7) * NCH1 + (k >> 6)) * 128 + r) * 64 + swz(k & 63, r);
    g_w1[dst] = __float2half(v);
}
__global__ void prep_bias(const float* __restrict__ bi0, const float* __restrict__ bh0,
                          const float* __restrict__ bi1, const float* __restrict__ bh1) {
    int n = blockIdx.x * blockDim.x + threadIdx.x;
    if (n >= G4) return;
    int row = (n & 3) * HID + (n >> 2);
    g_b0[n] = bi0[row] + bh0[row];
    g_b1[n] = bi1[row] + bh1[row];
}
__global__ void prep_xpad(const float* __restrict__ x) {
    int idx = blockIdx.x * blockDim.x + threadIdx.x;
    if (idx >= SEQ * BATCH * 64) return;
    int k = idx & 63, b = (idx >> 6) & 511, t = idx >> 15;
    float v = (k < 32) ? x[((size_t)t * BATCH + b) * 32 + k] : 0.0f;
    g_xp[((size_t)t * BATCH + b) * 64 + swz(k, b)] = __float2half(v);
}
__global__ void init_state(const float* __restrict__ h0in, const float* __restrict__ c0in) {
    int idx = blockIdx.x * blockDim.x + threadIdx.x;
    if (idx >= BATCH * HID) return;
    int b = idx >> 9, j = idx & (HID - 1);
    size_t dst = ((size_t)(j >> 6) * BATCH + b) * 64 + swz(j & 63, b);
    g_h0[0][dst] = __float2half(h0in[j]);
    g_h1[0][dst] = __float2half(h0in[HID + j]);
    g_c0[idx] = c0in[j];
    g_c1[idx] = c0in[HID + j];
}

// ---------------- cell machinery ----------------
struct CellP {
    const __half* slab0;   // chunk0 A bulk source (encoder l0) or null
    const __half* a1;      // h chunks
    const __half* a2;      // h chunks 8..15 (l1)
    const char* wglob;     // streaming B slice (l1)
    int nload, coff;
    bool resB, tail0;
    const float* bias;
    float* cbuf;
    __half* hOut;
    float* hOutF;
};

__device__ __forceinline__ void mma_chunk(uint32_t aB, uint32_t bB, float acc[4][4],
                                          int l, int wm, int wn) {
    const uint32_t aRow = (uint32_t)(wm * 16 + (l & 15));
    const uint32_t aQl = (uint32_t)(l >> 4);
    const uint32_t bRowB = (uint32_t)(wn * 32 + (l & 7) + ((l >> 4) & 1) * 8);
    const uint32_t bQl = (uint32_t)((l >> 3) & 1);
#pragma unroll
    for (int ks = 0; ks < 4; ++ks) {
        const uint32_t qa = aQl + ks * 2;
        uint32_t a[4];
        ldsm4(a, aB + aRow * 128 + ((qa ^ (aRow & 7)) << 4));
        uint32_t b[4][2];
#pragma unroll
        for (int ntp = 0; ntp < 2; ++ntp) {
            const uint32_t br = bRowB + ntp * 16;
            const uint32_t qb = bQl + ks * 2;
            uint32_t r4[4];
            ldsm4(r4, bB + br * 128 + ((qb ^ (br & 7)) << 4));
            b[ntp * 2][0] = r4[0]; b[ntp * 2][1] = r4[1];
            b[ntp * 2 + 1][0] = r4[2]; b[ntp * 2 + 1][1] = r4[3];
        }
#pragma unroll
        for (int nt = 0; nt < 4; ++nt)
            mma16816(acc[nt], a, b[nt]);
    }
}

__device__ unsigned cell(unsigned cg, uint32_t sb, const CellP& P, int n0, int m0) {
    const uint32_t ring = sb + RING_OFF, mb = sb + MBAR_OFF;
    const int tid = threadIdx.x, l = tid & 31, w = tid >> 5;
    const int wm = w & 3, wn = w >> 2;

    auto issue = [&](int k) {
        const unsigned g = cg + (unsigned)k;
        const uint32_t st = ring + (g % 3) * STAGE_B;
        const uint32_t m = mb + (g % 3) * 8;
        FENCE_ASYNC();
        MBAR_EXPECT_TX(m, P.resB ? A_TILE_B : STAGE_B);
        const char* srcA;
        if (P.slab0 != nullptr && k == 0) {
            srcA = (const char*)P.slab0 + (size_t)m0 * 128;
        } else {
            int s1 = k - (P.slab0 != nullptr ? 1 : 0) + P.coff - (P.resB ? P.coff : 0);
            // for decode (coff=1, no slab0): loaded chunk k maps to h chunk k
            s1 = (P.slab0 != nullptr) ? (k - 1) : (P.resB ? k : k);
            const __half* base = (s1 < 8) ? P.a1 : P.a2;
            if (s1 >= 8) s1 -= 8;
            srcA = (const char*)base + (size_t)s1 * CHSLAB + (size_t)m0 * 128;
        }
        cpbulk(st, srcA, A_TILE_B, m);
        if (!P.resB)
            cpbulk(st + A_TILE_B, P.wglob + (size_t)k * B_TILE_B, B_TILE_B, m);
    };

    if (tid == 0) { issue(0); issue(1); }

    float acc[4][4];
#pragma unroll
    for (int nt = 0; nt < 4; ++nt)
#pragma unroll
        for (int i = 0; i < 4; ++i) acc[nt][i] = 0.0f;

    for (int k = 0; k < P.nload; ++k) {
        if (k > 0) __syncthreads();
        if (tid == 0 && k + 2 < P.nload) issue(k + 2);
        const unsigned g = cg + (unsigned)k;
        mbar_wait(mb + (g % 3) * 8, (g / 3) & 1);
        const uint32_t stage = ring + (g % 3) * STAGE_B;
        const uint32_t bB = P.resB ? (sb + (uint32_t)(P.coff + k) * B_TILE_B)
                                   : (stage + A_TILE_B);
        mma_chunk(stage, bB, acc, l, wm, wn);
    }
    if (P.tail0) {
        mma_chunk(sb + C0A_OFF, sb /* w0 tile 0 */, acc, l, wm, wn);
        __syncthreads();   // protect C0A (stage-2 B-half) from next cell's issues
    }

    // epilogue
    const bool odd = (l & 1) != 0;
#pragma unroll
    for (int nt = 0; nt < 4; ++nt) {
        float* cc = acc[nt];
        float send1 = odd ? cc[0] : cc[2];
        float send2 = odd ? cc[1] : cc[3];
        float r1 = __shfl_xor_sync(0xffffffffu, send1, 1);
        float r2 = __shfl_xor_sync(0xffffffffu, send2, 1);
        float gi, gf, gg, go;
        if (!odd) { gi = cc[0]; gf = cc[1]; gg = r1; go = r2; }
        else      { gi = r1;    gf = r2;    gg = cc[2]; go = cc[3]; }

        const int j = ((n0 + wn * 32 + nt * 8) >> 2) + ((l & 3) >> 1);
        const float4 b4 = *(const float4*)(P.bias + 4 * j);
        gi += b4.x; gf += b4.y; gg += b4.z; go += b4.w;

        const int bglob = m0 + wm * 16 + (l >> 2) + (odd ? 8 : 0);
        const int ix = bglob * HID + j;
        float cp = P.cbuf[ix];
        float cn = sigf(gf) * cp + sigf(gi) * tanhf(gg);
        float hn = sigf(go) * tanhf(cn);
        P.cbuf[ix] = cn;
        P.hOut[((size_t)(j >> 6) * BATCH + bglob) * 64 + swz(j & 63, bglob)] =
            __float2half(hn);
        if (P.hOutF != nullptr) P.hOutF[ix] = hn;
    }
    return cg + (unsigned)P.nload;
}

// ---------------- the persistent kernel ----------------
__global__ __launch_bounds__(THREADS, 1)
void lstm_persist(const float* __restrict__ ft,
                  const float* __restrict__ fcw,
                  const float* __restrict__ fcb,
                  float* __restrict__ out)
{
    extern __shared__ char smem[];
    const uint32_t sb = smem_u32(smem);
    const int tid = threadIdx.x;
    const int n0 = blockIdx.x * 128;
    const int m0 = blockIdx.y * 64;

    // init mbars + resident w0 tiles
    if (tid == 0) {
#pragma unroll
        for (int s = 0; s < 3; ++s) MBAR_INIT(sb + MBAR_OFF + s * 8, 1);
        MBAR_INIT(sb + MBAR_OFF + 24, 1);
        FENCE_ASYNC();
        MBAR_EXPECT_TX(sb + MBAR_OFF + 24, W0_B);
        cpbulk(sb, (const char*)g_w0 + (size_t)blockIdx.x * W0_B, W0_B,
               sb + MBAR_OFF + 24);
    }
    __syncthreads();
    mbar_wait(sb + MBAR_OFF + 24, 0);

    const char* w1slice = (const char*)g_w1 + (size_t)blockIdx.x * NCH1 * B_TILE_B;
    unsigned cg = 0;

    auto fc_slab = [&](int d) {   // build decode input slab in C0A; write out row d
        const int row = tid >> 3, o = tid & 7, b = m0 + row;
        const float4* h4 = (const float4*)(g_h1f + (size_t)b * HID);
        const float4* w4 = (const float4*)(fcw + (size_t)o * HID);
        float s = fcb[o];
#pragma unroll 4
        for (int j = 0; j < HID / 4; ++j) {
            float4 a = __ldcg(h4 + j);
            float4 wv = __ldg(w4 + j);
            s += a.x * wv.x + a.y * wv.y + a.z * wv.z + a.w * wv.w;
        }
        char* c0a = smem + C0A_OFF - 0;  // byte offset within dynamic smem
        *(__half*)(smem + C0A_OFF + row * 128 + 2 * swz(o, row)) = __float2half(s);
#pragma unroll
        for (int m = 0; m < 3; ++m) {
            int k = 8 + o * 3 + m;
            float v = __ldg(&ft[((size_t)d * BATCH + b) * TF_DIM + o * 3 + m]);
            *(__half*)(smem + C0A_OFF + row * 128 + 2 * swz(k, row)) = __float2half(v);
        }
#pragma unroll
        for (int z = 0; z < 4; ++z) {
            int k = 32 + o * 4 + z;
            *(__half*)(smem + C0A_OFF + row * 128 + 2 * swz(k, row)) = __half(0.0f);
        }
        if (blockIdx.x == 0)
            out[((size_t)d * BATCH + b) * OUT_DIM + o] = s;
        __syncthreads();
        (void)c0a;
    };

    // encoder l0(0)
    {
        CellP P = {};
        P.slab0 = g_xp; P.a1 = g_h0[0];
        P.nload = NCH0; P.resB = true; P.coff = 0;
        P.bias = g_b0; P.cbuf = g_c0; P.hOut = g_h0[1];
        cg = cell(cg, sb, P, n0, m0);
    }
    gridbar();

    for (int s = 0; s < 175; ++s) {
        // l1(s): h0(s+1), h1(s) -> h1(s+1)
        {
            CellP P = {};
            P.a1 = g_h0[(s + 1) & 1]; P.a2 = g_h1[s & 1];
            P.wglob = w1slice; P.nload = NCH1; P.resB = false;
            P.bias = g_b1; P.cbuf = g_c1; P.hOut = g_h1[(s + 1) & 1];
            P.hOutF = (s >= 127) ? g_h1f : nullptr;
            cg = cell(cg, sb, P, n0, m0);
        }
        if (s < 127) {
            // paired encoder l0(s+1): x[s+1], h0(s+1) -> h0(s+2)
            CellP P = {};
            P.slab0 = g_xp + (size_t)(s + 1) * BATCH * 64;
            P.a1 = g_h0[(s + 1) & 1];
            P.nload = NCH0; P.resB = true; P.coff = 0;
            P.bias = g_b0; P.cbuf = g_c0; P.hOut = g_h0[s & 1];
            cg = cell(cg, sb, P, n0, m0);
            gridbar();
        } else if (s < 174) {
            gridbar();
            const int d = s - 127;
            fc_slab(d);                       // y_d + tf_d -> C0A, out row d
            CellP P = {};                     // decode l0(s+1)
            P.a1 = g_h0[(s + 1) & 1];
            P.nload = 8; P.resB = true; P.coff = 1; P.tail0 = true;
            P.bias = g_b0; P.cbuf = g_c0; P.hOut = g_h0[s & 1];
            cg = cell(cg, sb, P, n0, m0);
            gridbar();
        } else {
            gridbar();
            // final fc: out row 47 (x==0 CTAs)
            if (blockIdx.x == 0) {
                const int row = tid >> 3, o = tid & 7, b = m0 + row;
                const float4* h4 = (const float4*)(g_h1f + (size_t)b * HID);
                const float4* w4 = (const float4*)(fcw + (size_t)o * HID);
                float v = fcb[o];
#pragma unroll 4
                for (int j = 0; j < HID / 4; ++j) {
                    float4 a = __ldcg(h4 + j);
                    float4 wv = __ldg(w4 + j);
                    v += a.x * wv.x + a.y * wv.y + a.z * wv.z + a.w * wv.w;
                }
                out[((size_t)(FUT - 1) * BATCH + b) * OUT_DIM + o] = v;
            }
        }
    }
}

// ---------------- host orchestration ----------------
extern "C" void kernel_launch(void* const* d_in, const int* in_sizes, int n_in,
                              void* d_out, int out_size) {
    const float* x     = (const float*)d_in[0];
    const float* ft    = (const float*)d_in[1];
    const float* h0in  = (const float*)d_in[2];
    const float* c0in  = (const float*)d_in[3];
    const float* w_ih0 = (const float*)d_in[4];
    const float* w_hh0 = (const float*)d_in[5];
    const float* b_ih0 = (const float*)d_in[6];
    const float* b_hh0 = (const float*)d_in[7];
    const float* w_ih1 = (const float*)d_in[8];
    const float* w_hh1 = (const float*)d_in[9];
    const float* b_ih1 = (const float*)d_in[10];
    const float* b_hh1 = (const float*)d_in[11];
    const float* fcw   = (const float*)d_in[12];
    const float* fcb   = (const float*)d_in[13];
    float* out = (float*)d_out;

    cudaFuncSetAttribute(lstm_persist, cudaFuncAttributeMaxDynamicSharedMemorySize,
                         SMEM_TOT);

    prep_w0<<<(G4 * KTOT0 + 255) / 256, 256>>>(w_ih0, w_hh0);
    prep_w1<<<(G4 * KTOT1 + 255) / 256, 256>>>(w_ih1, w_hh1);
    prep_bias<<<(G4 + 255) / 256, 256>>>(b_ih0, b_hh0, b_ih1, b_hh1);
    prep_xpad<<<(SEQ * BATCH * 64 + 255) / 256, 256>>>(x);
    init_state<<<(BATCH * HID + 255) / 256, 256>>>(h0in, c0in);

    lstm_persist<<<dim3(16, 8), THREADS, SMEM_TOT>>>(ft, fcw, fcb, out);
}

// round 10
// speedup vs baseline: 1.1917x; 1.1917x over previous
#include <cuda_runtime.h>
#include <cuda_fp16.h>
#include <cstdint>

#define HID 512
#define BATCH 512
#define G4 2048
#define NCH0 9
#define NCH1 16
#define KTOT0 576
#define KTOT1 1024
#define SEQ 128
#define FUT 48
#define TF_DIM 24
#define OUT_DIM 8

#define THREADS 256
#define A_TILE_B 8192
#define B_TILE_B 16384
#define STAGE_B (A_TILE_B + B_TILE_B)   // 24576
#define SLAB_OFF (3 * STAGE_B)          // 73728
#define MBAR_OFF (SLAB_OFF + A_TILE_B)  // 81920
#define SMEM_B (MBAR_OFF + 64)          // 81984  (x2 CTAs = 163968 <= 227KB)
#define CHSLAB 65536                    // bytes per (chunk, full-batch) A slab

// ---------------- persistent device buffers (chunk-tiled, pre-swizzled) ----------
__device__ __align__(256) __half g_w0[16 * NCH0 * 128 * 64];
__device__ __align__(256) __half g_w1[16 * NCH1 * 128 * 64];
__device__ __align__(256) __half g_xp[SEQ * BATCH * 64];
__device__ __align__(256) __half g_h0[2][BATCH * HID];
__device__ __align__(256) __half g_h1[2][BATCH * HID];
__device__ __align__(256) float g_h1f[BATCH * HID];
__device__ __align__(256) float g_c0[BATCH * HID];
__device__ __align__(256) float g_c1[BATCH * HID];
__device__ __align__(256) float g_b0[G4];
__device__ __align__(256) float g_b1[G4];

// ---------------- helpers ----------------
__device__ __forceinline__ int swz(int k, int r) {
    return (((k >> 3) ^ (r & 7)) << 3) | (k & 7);
}
__device__ __forceinline__ uint32_t smem_u32(const void* p) {
    uint32_t a;
    asm("{ .reg .u64 t; cvta.to.shared.u64 t, %1; cvt.u32.u64 %0, t; }" : "=r"(a) : "l"(p));
    return a;
}
__device__ __forceinline__ void cpbulk(uint32_t dst, const void* src, uint32_t bytes,
                                       uint32_t mbar) {
    asm volatile(
        "cp.async.bulk.shared::cluster.global.mbarrier::complete_tx::bytes "
        "[%0], [%1], %2, [%3];"
        :: "r"(dst), "l"(src), "r"(bytes), "r"(mbar) : "memory");
}
#define FENCE_ASYNC() asm volatile("fence.proxy.async.shared::cta;" ::: "memory")
#define MBAR_INIT(a, n) asm volatile("mbarrier.init.shared.b64 [%0], %1;" :: "r"(a), "r"(n) : "memory")
#define MBAR_EXPECT_TX(a, tx) asm volatile("mbarrier.arrive.expect_tx.shared.b64 _, [%0], %1;" :: "r"(a), "r"(tx) : "memory")

__device__ __forceinline__ void mbar_wait(uint32_t mbar, uint32_t parity) {
    asm volatile(
        "{\n\t.reg .pred P1;\n\t"
        "WL_%=:\n\t"
        "mbarrier.try_wait.parity.acquire.cta.shared::cta.b64 P1, [%0], %1, 0x989680;\n\t"
        "@P1 bra.uni WD_%=;\n\t"
        "bra.uni WL_%=;\n\t"
        "WD_%=:\n\t}"
        :: "r"(mbar), "r"(parity) : "memory");
}
__device__ __forceinline__ void ldsm4(uint32_t* r, uint32_t addr) {
    asm volatile("ldmatrix.sync.aligned.m8n8.x4.shared.b16 {%0,%1,%2,%3}, [%4];"
                 : "=r"(r[0]), "=r"(r[1]), "=r"(r[2]), "=r"(r[3]) : "r"(addr));
}
__device__ __forceinline__ void mma16816(float* c, const uint32_t* a, const uint32_t* b) {
    asm volatile(
        "mma.sync.aligned.m16n8k16.row.col.f32.f16.f16.f32 "
        "{%0,%1,%2,%3}, {%4,%5,%6,%7}, {%8,%9}, {%0,%1,%2,%3};"
        : "+f"(c[0]), "+f"(c[1]), "+f"(c[2]), "+f"(c[3])
        : "r"(a[0]), "r"(a[1]), "r"(a[2]), "r"(a[3]), "r"(b[0]), "r"(b[1]));
}
__device__ __forceinline__ float sigf(float x) { return 1.0f / (1.0f + __expf(-x)); }

// ---------------- prep kernels ----------------
__global__ void prep_w0(const float* __restrict__ wih, const float* __restrict__ whh) {
    int idx = blockIdx.x * blockDim.x + threadIdx.x;
    if (idx >= G4 * KTOT0) return;
    int n = idx / KTOT0, k = idx - n * KTOT0;
    int row = (n & 3) * HID + (n >> 2);
    float v;
    if (k < 64) v = (k < 32) ? wih[row * 32 + k] : 0.0f;
    else        v = whh[row * HID + (k - 64)];
    int r = n & 127;
    size_t dst = ((size_t)((n >> 7) * NCH0 + (k >> 6)) * 128 + r) * 64 + swz(k & 63, r);
    g_w0[dst] = __float2half(v);
}
__global__ void prep_w1(const float* __restrict__ wih, const float* __restrict__ whh) {
    int idx = blockIdx.x * blockDim.x + threadIdx.x;
    if (idx >= G4 * KTOT1) return;
    int n = idx >> 10, k = idx & 1023;
    int row = (n & 3) * HID + (n >> 2);
    float v = (k < HID) ? wih[row * HID + k] : whh[row * HID + (k - HID)];
    int r = n & 127;
    size_t dst = ((size_t)((n >> 7) * NCH1 + (k >> 6)) * 128 + r) * 64 + swz(k & 63, r);
    g_w1[dst] = __float2half(v);
}
__global__ void prep_bias(const float* __restrict__ bi0, const float* __restrict__ bh0,
                          const float* __restrict__ bi1, const float* __restrict__ bh1) {
    int n = blockIdx.x * blockDim.x + threadIdx.x;
    if (n >= G4) return;
    int row = (n & 3) * HID + (n >> 2);
    g_b0[n] = bi0[row] + bh0[row];
    g_b1[n] = bi1[row] + bh1[row];
}
__global__ void prep_xpad(const float* __restrict__ x) {
    int idx = blockIdx.x * blockDim.x + threadIdx.x;
    if (idx >= SEQ * BATCH * 64) return;
    int k = idx & 63, b = (idx >> 6) & 511, t = idx >> 15;
    float v = (k < 32) ? x[((size_t)t * BATCH + b) * 32 + k] : 0.0f;
    g_xp[((size_t)t * BATCH + b) * 64 + swz(k, b)] = __float2half(v);
}
__global__ void init_state(const float* __restrict__ h0in, const float* __restrict__ c0in) {
    int idx = blockIdx.x * blockDim.x + threadIdx.x;
    if (idx >= BATCH * HID) return;
    int b = idx >> 9, j = idx & (HID - 1);
    size_t dst = ((size_t)(j >> 6) * BATCH + b) * 64 + swz(j & 63, b);
    g_h0[0][dst] = __float2half(h0in[j]);
    g_h1[0][dst] = __float2half(h0in[HID + j]);
    g_c0[idx] = c0in[j];
    g_c1[idx] = c0in[HID + j];
}

// ---------------- cell parameters ----------------
struct CellP {
    const __half* slab0;    // gmem chunk0 A slab (encoder l0); null otherwise
    int smemSlab0;          // decode l0: chunk0 A built in smem (fc prologue)
    const __half* a1;       // h chunks 0..7
    const __half* a2;       // h chunks 8..15 (l1)
    const __half* wt;       // weight tile array base (g_w0 / g_w1)
    int nch;
    const float* bias;
    float* cbuf;
    __half* hOut;
    float* hOutF;
    // decode extras
    const float* h1fprev;
    const float* fcw;
    const float* fcb;
    const float* tfrow;
    float* outrow;
};

// ---------------- fused LSTM cell (8 warps, 64x128 tile, 3-stage bulk) ----------
__global__ __launch_bounds__(THREADS, 2)
void lstm_cell(CellP A0, CellP A1)
{
    const CellP P = blockIdx.z ? A1 : A0;
    extern __shared__ char smem[];
    const uint32_t sb = smem_u32(smem);
    const uint32_t mb = sb + MBAR_OFF;
    const uint32_t slab = sb + SLAB_OFF;

    const int tid = threadIdx.x;
    const int l = tid & 31, w = tid >> 5;
    const int wm = w & 1;          // 0..1 : 32-row slab
    const int wn = w >> 1;         // 0..3 : 32-col slab
    const int n0 = blockIdx.x * 128;
    const int m0 = blockIdx.y * 64;
    const bool sk0 = (P.smemSlab0 != 0);
    const int nch = P.nch;

    if (tid == 0) {
#pragma unroll
        for (int s = 0; s < 3; ++s) MBAR_INIT(mb + s * 8, 1);
    }
    __syncthreads();

    const char* wbase = (const char*)P.wt + (size_t)blockIdx.x * nch * B_TILE_B;

    auto issue = [&](int k) {
        const uint32_t st = sb + (uint32_t)(k % 3) * STAGE_B;
        const uint32_t m = mb + (uint32_t)(k % 3) * 8;
        const bool aload = !(sk0 && k == 0);
        FENCE_ASYNC();
        MBAR_EXPECT_TX(m, (aload ? A_TILE_B : 0) + B_TILE_B);
        if (aload) {
            const char* srcA;
            if (k == 0 && P.slab0 != nullptr) {
                srcA = (const char*)P.slab0 + (size_t)m0 * 128;
            } else {
                int s1 = k - ((P.slab0 != nullptr || sk0) ? 1 : 0);
                const __half* base = (s1 < 8) ? P.a1 : P.a2;
                if (s1 >= 8) s1 -= 8;
                srcA = (const char*)base + (size_t)s1 * CHSLAB + (size_t)m0 * 128;
            }
            cpbulk(st, srcA, A_TILE_B, m);
        }
        cpbulk(st + A_TILE_B, wbase + (size_t)k * B_TILE_B, B_TILE_B, m);
    };

    if (tid == 0) { issue(0); issue(1); }

    // decode-l0 prologue: y = fc(h1f) (fp32), build swizzled input slab in smem
    if (sk0) {
        const int o = tid & 7, r0 = tid >> 3;     // r0: 0..31
#pragma unroll
        for (int half2i = 0; half2i < 2; ++half2i) {
            const int rr = r0 + half2i * 32;
            const int b = m0 + rr;
            const float4* h4 = (const float4*)(P.h1fprev + (size_t)b * HID);
            const float4* w4 = (const float4*)(P.fcw + (size_t)o * HID);
            float s = P.fcb[o];
#pragma unroll 4
            for (int j = 0; j < HID / 4; ++j) {
                float4 a = __ldg(h4 + j), wv = __ldg(w4 + j);
                s += a.x * wv.x + a.y * wv.y + a.z * wv.z + a.w * wv.w;
            }
            char* rowp = smem + SLAB_OFF + rr * 128;
            *(__half*)(rowp + 2 * swz(o, rr)) = __float2half(s);
#pragma unroll
            for (int m = 0; m < 3; ++m) {
                int kk = 8 + o * 3 + m;
                float v = __ldg(&P.tfrow[(size_t)b * TF_DIM + o * 3 + m]);
                *(__half*)(rowp + 2 * swz(kk, rr)) = __float2half(v);
            }
#pragma unroll
            for (int z = 0; z < 4; ++z) {
                int kk = 32 + o * 4 + z;
                *(__half*)(rowp + 2 * swz(kk, rr)) = __half(0.0f);
            }
            if (blockIdx.x == 0)
                P.outrow[(size_t)b * OUT_DIM + o] = s;
        }
        __syncthreads();
    }

    float acc[2][4][4];
#pragma unroll
    for (int mt = 0; mt < 2; ++mt)
#pragma unroll
        for (int nt = 0; nt < 4; ++nt)
#pragma unroll
            for (int i = 0; i < 4; ++i) acc[mt][nt][i] = 0.0f;

    const uint32_t aQl = (uint32_t)(l >> 4);
    const uint32_t bRowB = (uint32_t)(wn * 32 + (l & 7) + ((l >> 4) & 1) * 8);
    const uint32_t bQl = (uint32_t)((l >> 3) & 1);

    for (int k = 0; k < nch; ++k) {
        if (k > 0) __syncthreads();
        if (tid == 0 && k + 2 < nch) issue(k + 2);
        mbar_wait(mb + (uint32_t)(k % 3) * 8, (uint32_t)((k / 3) & 1));
        const uint32_t stage = sb + (uint32_t)(k % 3) * STAGE_B;
        const uint32_t aB = (sk0 && k == 0) ? slab : stage;
        const uint32_t bB = stage + A_TILE_B;

#pragma unroll
        for (int ks = 0; ks < 4; ++ks) {
            const uint32_t qa = aQl + ks * 2;
            uint32_t a[2][4];
#pragma unroll
            for (int mt = 0; mt < 2; ++mt) {
                const uint32_t ar = (uint32_t)(wm * 32 + mt * 16 + (l & 15));
                ldsm4(a[mt], aB + ar * 128 + ((qa ^ (ar & 7)) << 4));
            }
            uint32_t b[4][2];
#pragma unroll
            for (int ntp = 0; ntp < 2; ++ntp) {
                const uint32_t br = bRowB + ntp * 16;
                const uint32_t qb = bQl + ks * 2;
                uint32_t r4[4];
                ldsm4(r4, bB + br * 128 + ((qb ^ (br & 7)) << 4));
                b[ntp * 2][0] = r4[0]; b[ntp * 2][1] = r4[1];
                b[ntp * 2 + 1][0] = r4[2]; b[ntp * 2 + 1][1] = r4[3];
            }
#pragma unroll
            for (int mt = 0; mt < 2; ++mt)
#pragma unroll
                for (int nt = 0; nt < 4; ++nt)
                    mma16816(acc[mt][nt], a[mt], b[nt]);
        }
    }

    // ---- epilogue: assemble gates via lane-pair exchange, LSTM update ----
    const bool odd = (l & 1) != 0;
#pragma unroll
    for (int mt = 0; mt < 2; ++mt)
#pragma unroll
        for (int nt = 0; nt < 4; ++nt) {
            float* cc = acc[mt][nt];
            float send1 = odd ? cc[0] : cc[2];
            float send2 = odd ? cc[1] : cc[3];
            float r1 = __shfl_xor_sync(0xffffffffu, send1, 1);
            float r2 = __shfl_xor_sync(0xffffffffu, send2, 1);
            float gi, gf, gg, go;
            if (!odd) { gi = cc[0]; gf = cc[1]; gg = r1; go = r2; }
            else      { gi = r1;    gf = r2;    gg = cc[2]; go = cc[3]; }

            const int j = ((n0 + wn * 32 + nt * 8) >> 2) + ((l & 3) >> 1);
            const float4 b4 = *(const float4*)(P.bias + 4 * j);
            gi += b4.x; gf += b4.y; gg += b4.z; go += b4.w;

            const int bglob = m0 + wm * 32 + mt * 16 + (l >> 2) + (odd ? 8 : 0);
            const int ix = bglob * HID + j;
            float cp = P.cbuf[ix];
            float cn = sigf(gf) * cp + sigf(gi) * tanhf(gg);
            float hn = sigf(go) * tanhf(cn);
            P.cbuf[ix] = cn;
            P.hOut[((size_t)(j >> 6) * BATCH + bglob) * 64 + swz(j & 63, bglob)] =
                __float2half(hn);
            if (P.hOutF != nullptr) P.hOutF[ix] = hn;
        }
}

// ---------------- final output row ----------------
__global__ void fc_out(const float* __restrict__ h1f,
                       const float* __restrict__ fcw, const float* __restrict__ fcb,
                       float* __restrict__ outp) {
    int idx = blockIdx.x * blockDim.x + threadIdx.x;   // 4096
    int b = idx >> 3, o = idx & 7;
    const float4* h4 = (const float4*)(h1f + (size_t)b * HID);
    const float4* w4 = (const float4*)(fcw + (size_t)o * HID);
    float s = fcb[o];
#pragma unroll 4
    for (int j = 0; j < HID / 4; ++j) {
        float4 a = h4[j], w = w4[j];
        s += a.x * w.x + a.y * w.y + a.z * w.z + a.w * w.w;
    }
    outp[b * OUT_DIM + o] = s;
}

// ---------------- host orchestration ----------------
extern "C" void kernel_launch(void* const* d_in, const int* in_sizes, int n_in,
                              void* d_out, int out_size) {
    const float* x     = (const float*)d_in[0];
    const float* ft    = (const float*)d_in[1];
    const float* h0in  = (const float*)d_in[2];
    const float* c0in  = (const float*)d_in[3];
    const float* w_ih0 = (const float*)d_in[4];
    const float* w_hh0 = (const float*)d_in[5];
    const float* b_ih0 = (const float*)d_in[6];
    const float* b_hh0 = (const float*)d_in[7];
    const float* w_ih1 = (const float*)d_in[8];
    const float* w_hh1 = (const float*)d_in[9];
    const float* b_ih1 = (const float*)d_in[10];
    const float* b_hh1 = (const float*)d_in[11];
    const float* fcw   = (const float*)d_in[12];
    const float* fcb   = (const float*)d_in[13];
    float* out = (float*)d_out;

    cudaFuncSetAttribute(lstm_cell, cudaFuncAttributeMaxDynamicSharedMemorySize, SMEM_B);

    __half *w0p, *w1p, *xp, *h0p, *h1p;
    float *h1fp, *c0p, *c1p, *b0p, *b1p;
    cudaGetSymbolAddress((void**)&w0p, g_w0);
    cudaGetSymbolAddress((void**)&w1p, g_w1);
    cudaGetSymbolAddress((void**)&xp, g_xp);
    cudaGetSymbolAddress((void**)&h0p, g_h0);
    cudaGetSymbolAddress((void**)&h1p, g_h1);
    cudaGetSymbolAddress((void**)&h1fp, g_h1f);
    cudaGetSymbolAddress((void**)&c0p, g_c0);
    cudaGetSymbolAddress((void**)&c1p, g_c1);
    cudaGetSymbolAddress((void**)&b0p, g_b0);
    cudaGetSymbolAddress((void**)&b1p, g_b1);

    prep_w0<<<(G4 * KTOT0 + 255) / 256, 256>>>(w_ih0, w_hh0);
    prep_w1<<<(G4 * KTOT1 + 255) / 256, 256>>>(w_ih1, w_hh1);
    prep_bias<<<(G4 + 255) / 256, 256>>>(b_ih0, b_hh0, b_ih1, b_hh1);
    prep_xpad<<<(SEQ * BATCH * 64 + 255) / 256, 256>>>(x);
    init_state<<<(BATCH * HID + 255) / 256, 256>>>(h0in, c0in);

    const int SN = BATCH * HID;
    CellP Z = {};

    auto mk_l0enc = [&](int s) {    // reads h0 state s (buf s&1) + x[s]; writes buf (s+1)&1
        CellP a = {};
        a.slab0 = xp + (size_t)s * BATCH * 64;
        a.a1 = h0p + (size_t)(s & 1) * SN;
        a.wt = w0p; a.nch = NCH0;
        a.bias = b0p; a.cbuf = c0p;
        a.hOut = h0p + (size_t)((s + 1) & 1) * SN;
        return a;
    };
    auto mk_l1 = [&](int s, bool wf) {  // reads h0 buf (s+1)&1, h1 buf s&1; writes h1 buf (s+1)&1
        CellP a = {};
        a.a1 = h0p + (size_t)((s + 1) & 1) * SN;
        a.a2 = h1p + (size_t)(s & 1) * SN;
        a.wt = w1p; a.nch = NCH1;
        a.bias = b1p; a.cbuf = c1p;
        a.hOut = h1p + (size_t)((s + 1) & 1) * SN;
        a.hOutF = wf ? h1fp : nullptr;
        return a;
    };
    auto mk_l0dec = [&](int d) {    // s = 128+d; fc prologue builds input slab
        CellP a = {};
        a.smemSlab0 = 1;
        a.a1 = h0p + (size_t)(d & 1) * SN;          // (128+d)&1 == d&1
        a.wt = w0p; a.nch = NCH0;
        a.bias = b0p; a.cbuf = c0p;
        a.hOut = h0p + (size_t)((d + 1) & 1) * SN;
        a.h1fprev = h1fp; a.fcw = fcw; a.fcb = fcb;
        a.tfrow = ft + (size_t)d * BATCH * TF_DIM;
        a.outrow = out + (size_t)d * BATCH * OUT_DIM;
        return a;
    };

    const dim3 gridS(16, 8, 1), gridC(16, 8, 2);

    // encoder
    lstm_cell<<<gridS, THREADS, SMEM_B>>>(mk_l0enc(0), Z);
    for (int t = 0; t < SEQ - 1; ++t)
        lstm_cell<<<gridC, THREADS, SMEM_B>>>(mk_l1(t, false), mk_l0enc(t + 1));
    lstm_cell<<<gridS, THREADS, SMEM_B>>>(mk_l1(SEQ - 1, true), Z);

    // autoregressive decode
    for (int d = 0; d < FUT - 1; ++d) {
        lstm_cell<<<gridS, THREADS, SMEM_B>>>(mk_l0dec(d), Z);
        lstm_cell<<<gridS, THREADS, SMEM_B>>>(mk_l1(SEQ + d, true), Z);
    }
    fc_out<<<16, 256>>>(h1fp, fcw, fcb, out + (size_t)(FUT - 1) * BATCH * OUT_DIM);
}

// round 11
// speedup vs baseline: 1.3201x; 1.1078x over previous
#include <cuda_runtime.h>
#include <cuda_fp16.h>
#include <cstdint>

#define HID 512
#define BATCH 512
#define G4 2048
#define NCH0 9
#define NCH1 16
#define KTOT0 576
#define KTOT1 1024
#define SEQ 128
#define FUT 48
#define TF_DIM 24
#define OUT_DIM 8

#define THREADS 512
#define A_TILE_B 8192
#define B_TILE_B 16384
#define STAGE_B (A_TILE_B + B_TILE_B)   // 24576
#define MBAR_OFF (3 * STAGE_B)          // 73728
#define SMEM_B (MBAR_OFF + 64)
#define CHSLAB 65536                    // bytes per (chunk, full-batch) A slab

// ---------------- persistent device buffers (chunk-tiled, pre-swizzled) ----------
__device__ __align__(256) __half g_w0[16 * NCH0 * 128 * 64];
__device__ __align__(256) __half g_w1[16 * NCH1 * 128 * 64];
__device__ __align__(256) __half g_xp[SEQ * BATCH * 64];
__device__ __align__(256) __half g_ip[BATCH * 64];
__device__ __align__(256) __half g_h0[2][BATCH * HID];
__device__ __align__(256) __half g_h1[2][BATCH * HID];
__device__ __align__(256) float g_h1f[BATCH * HID];
__device__ __align__(256) float g_c0[BATCH * HID];
__device__ __align__(256) float g_c1[BATCH * HID];
__device__ __align__(256) float g_b0[G4];
__device__ __align__(256) float g_b1[G4];

// ---------------- helpers ----------------
__device__ __forceinline__ int swz(int k, int r) {
    return (((k >> 3) ^ (r & 7)) << 3) | (k & 7);
}
__device__ __forceinline__ uint32_t smem_u32(const void* p) {
    uint32_t a;
    asm("{ .reg .u64 t; cvta.to.shared.u64 t, %1; cvt.u32.u64 %0, t; }" : "=r"(a) : "l"(p));
    return a;
}
__device__ __forceinline__ void cpbulk(uint32_t dst, const void* src, uint32_t bytes,
                                       uint32_t mbar) {
    asm volatile(
        "cp.async.bulk.shared::cluster.global.mbarrier::complete_tx::bytes "
        "[%0], [%1], %2, [%3];"
        :: "r"(dst), "l"(src), "r"(bytes), "r"(mbar) : "memory");
}
#define FENCE_ASYNC() asm volatile("fence.proxy.async.shared::cta;" ::: "memory")
#define MBAR_INIT(a, n) asm volatile("mbarrier.init.shared.b64 [%0], %1;" :: "r"(a), "r"(n) : "memory")
#define MBAR_EXPECT_TX(a, tx) asm volatile("mbarrier.arrive.expect_tx.shared.b64 _, [%0], %1;" :: "r"(a), "r"(tx) : "memory")

__device__ __forceinline__ void mbar_wait(uint32_t mbar, uint32_t parity) {
    asm volatile(
        "{\n\t.reg .pred P1;\n\t"
        "WL_%=:\n\t"
        "mbarrier.try_wait.parity.acquire.cta.shared::cta.b64 P1, [%0], %1, 0x989680;\n\t"
        "@P1 bra.uni WD_%=;\n\t"
        "bra.uni WL_%=;\n\t"
        "WD_%=:\n\t}"
        :: "r"(mbar), "r"(parity) : "memory");
}
__device__ __forceinline__ void ldsm4(uint32_t* r, uint32_t addr) {
    asm volatile("ldmatrix.sync.aligned.m8n8.x4.shared.b16 {%0,%1,%2,%3}, [%4];"
                 : "=r"(r[0]), "=r"(r[1]), "=r"(r[2]), "=r"(r[3]) : "r"(addr));
}
// fp16-accumulator HMMA (classically double-rate vs f32 acc)
__device__ __forceinline__ void mma16816h(uint32_t* d, const uint32_t* a,
                                          const uint32_t* b) {
    asm volatile(
        "mma.sync.aligned.m16n8k16.row.col.f16.f16.f16.f16 "
        "{%0,%1}, {%2,%3,%4,%5}, {%6,%7}, {%0,%1};"
        : "+r"(d[0]), "+r"(d[1])
        : "r"(a[0]), "r"(a[1]), "r"(a[2]), "r"(a[3]), "r"(b[0]), "r"(b[1]));
}
__device__ __forceinline__ float sigf(float x) { return 1.0f / (1.0f + __expf(-x)); }

// ---------------- prep kernels ----------------
__global__ void prep_w0(const float* __restrict__ wih, const float* __restrict__ whh) {
    int idx = blockIdx.x * blockDim.x + threadIdx.x;
    if (idx >= G4 * KTOT0) return;
    int n = idx / KTOT0, k = idx - n * KTOT0;
    int row = (n & 3) * HID + (n >> 2);
    float v;
    if (k < 64) v = (k < 32) ? wih[row * 32 + k] : 0.0f;
    else        v = whh[row * HID + (k - 64)];
    int r = n & 127;
    size_t dst = ((size_t)((n >> 7) * NCH0 + (k >> 6)) * 128 + r) * 64 + swz(k & 63, r);
    g_w0[dst] = __float2half(v);
}
__global__ void prep_w1(const float* __restrict__ wih, const float* __restrict__ whh) {
    int idx = blockIdx.x * blockDim.x + threadIdx.x;
    if (idx >= G4 * KTOT1) return;
    int n = idx >> 10, k = idx & 1023;
    int row = (n & 3) * HID + (n >> 2);
    float v = (k < HID) ? wih[row * HID + k] : whh[row * HID + (k - HID)];
    int r = n & 127;
    size_t dst = ((size_t)((n >> 7) * NCH1 + (k >> 6)) * 128 + r) * 64 + swz(k & 63, r);
    g_w1[dst] = __float2half(v);
}
__global__ void prep_bias(const float* __restrict__ bi0, const float* __restrict__ bh0,
                          const float* __restrict__ bi1, const float* __restrict__ bh1) {
    int n = blockIdx.x * blockDim.x + threadIdx.x;
    if (n >= G4) return;
    int row = (n & 3) * HID + (n >> 2);
    g_b0[n] = bi0[row] + bh0[row];
    g_b1[n] = bi1[row] + bh1[row];
}
__global__ void prep_xpad(const float* __restrict__ x) {
    int idx = blockIdx.x * blockDim.x + threadIdx.x;
    if (idx >= SEQ * BATCH * 64) return;
    int k = idx & 63, b = (idx >> 6) & 511, t = idx >> 15;
    float v = (k < 32) ? x[((size_t)t * BATCH + b) * 32 + k] : 0.0f;
    g_xp[((size_t)t * BATCH + b) * 64 + swz(k, b)] = __float2half(v);
}
__global__ void prep_ipzero() {
    int idx = blockIdx.x * blockDim.x + threadIdx.x;
    if (idx < BATCH * 64) g_ip[idx] = __float2half(0.0f);
}
__global__ void init_state(const float* __restrict__ h0in, const float* __restrict__ c0in) {
    int idx = blockIdx.x * blockDim.x + threadIdx.x;
    if (idx >= BATCH * HID) return;
    int b = idx >> 9, j = idx & (HID - 1);
    size_t dst = ((size_t)(j >> 6) * BATCH + b) * 64 + swz(j & 63, b);
    g_h0[0][dst] = __float2half(h0in[j]);
    g_h1[0][dst] = __float2half(h0in[HID + j]);
    g_c0[idx] = c0in[j];
    g_c1[idx] = c0in[HID + j];
}

// ---------------- cell parameters ----------------
struct CellP {
    const __half* slab0;    // chunk0 A slab (xp row / g_ip) or null
    const __half* a1;       // h chunks 0..7
    const __half* a2;       // h chunks 8..15 (l1)
    const __half* wt;       // weight tile base (g_w0 / g_w1)
    int nch;
    const float* bias;
    float* cbuf;
    __half* hOut;
    float* hOutF;
};

// ---------------- fused LSTM cell (16 warps, 64x128 tile, 3-stage bulk) ---------
__global__ __launch_bounds__(THREADS, 1)
void lstm_cell(CellP A0, CellP A1)
{
    const CellP P = blockIdx.z ? A1 : A0;
    extern __shared__ char smem_raw[];
    const uint32_t sb = smem_u32(smem_raw);
    const uint32_t mb = sb + MBAR_OFF;
    const int tid = threadIdx.x;
    const int l = tid & 31, w = tid >> 5;
    const int wm = w & 3;          // 0..3 : 16-row slab
    const int wn = w >> 2;         // 0..3 : 32-col slab
    const int n0 = blockIdx.x * 128;
    const int m0 = blockIdx.y * 64;
    const int nch = P.nch;

    if (tid == 0) {
#pragma unroll
        for (int s = 0; s < 3; ++s) MBAR_INIT(mb + s * 8, 1);
    }
    __syncthreads();

    const char* wbase = (const char*)P.wt + (size_t)blockIdx.x * nch * B_TILE_B;

    auto issue = [&](int k) {
        const uint32_t st = sb + (uint32_t)(k % 3) * STAGE_B;
        const uint32_t m = mb + (uint32_t)(k % 3) * 8;
        FENCE_ASYNC();
        MBAR_EXPECT_TX(m, STAGE_B);
        const char* srcA;
        if (k == 0 && P.slab0 != nullptr) {
            srcA = (const char*)P.slab0 + (size_t)m0 * 128;
        } else {
            int s1 = k - (P.slab0 != nullptr ? 1 : 0);
            const __half* base = (s1 < 8) ? P.a1 : P.a2;
            if (s1 >= 8) s1 -= 8;
            srcA = (const char*)base + (size_t)s1 * CHSLAB + (size_t)m0 * 128;
        }
        cpbulk(st, srcA, A_TILE_B, m);
        cpbulk(st + A_TILE_B, wbase + (size_t)k * B_TILE_B, B_TILE_B, m);
    };

    if (tid == 0) { issue(0); issue(1); }

    float acc[4][4];
#pragma unroll
    for (int nt = 0; nt < 4; ++nt)
#pragma unroll
        for (int i = 0; i < 4; ++i) acc[nt][i] = 0.0f;

    const uint32_t aRow = (uint32_t)(wm * 16 + (l & 15));
    const uint32_t aQl = (uint32_t)(l >> 4);
    const uint32_t bRowB = (uint32_t)(wn * 32 + (l & 7) + ((l >> 4) & 1) * 8);
    const uint32_t bQl = (uint32_t)((l >> 3) & 1);

    for (int k = 0; k < nch; ++k) {
        if (k > 0) __syncthreads();
        if (tid == 0 && k + 2 < nch) issue(k + 2);
        mbar_wait(mb + (uint32_t)(k % 3) * 8, (uint32_t)((k / 3) & 1));
        const uint32_t stage = sb + (uint32_t)(k % 3) * STAGE_B;

        // fp16 accumulators for this chunk only (4 chained MMAs), then fold to fp32
        uint32_t d16[4][2];
#pragma unroll
        for (int nt = 0; nt < 4; ++nt) { d16[nt][0] = 0u; d16[nt][1] = 0u; }

#pragma unroll
        for (int ks = 0; ks < 4; ++ks) {
            const uint32_t qa = aQl + ks * 2;
            uint32_t a[4];
            ldsm4(a, stage + aRow * 128 + ((qa ^ (aRow & 7)) << 4));
            uint32_t b[4][2];
#pragma unroll
            for (int ntp = 0; ntp < 2; ++ntp) {
                const uint32_t br = bRowB + ntp * 16;
                const uint32_t qb = bQl + ks * 2;
                uint32_t r4[4];
                ldsm4(r4, stage + A_TILE_B + br * 128 + ((qb ^ (br & 7)) << 4));
                b[ntp * 2][0] = r4[0]; b[ntp * 2][1] = r4[1];
                b[ntp * 2 + 1][0] = r4[2]; b[ntp * 2 + 1][1] = r4[3];
            }
#pragma unroll
            for (int nt = 0; nt < 4; ++nt)
                mma16816h(d16[nt], a, b[nt]);
        }
#pragma unroll
        for (int nt = 0; nt < 4; ++nt) {
            float2 p0 = __half22float2(*(const __half2*)&d16[nt][0]);
            float2 p1 = __half22float2(*(const __half2*)&d16[nt][1]);
            acc[nt][0] += p0.x; acc[nt][1] += p0.y;
            acc[nt][2] += p1.x; acc[nt][3] += p1.y;
        }
    }

    // ---- epilogue: assemble gates via lane-pair exchange, LSTM update ----
    const bool odd = (l & 1) != 0;
#pragma unroll
    for (int nt = 0; nt < 4; ++nt) {
        float* cc = acc[nt];
        float send1 = odd ? cc[0] : cc[2];
        float send2 = odd ? cc[1] : cc[3];
        float r1 = __shfl_xor_sync(0xffffffffu, send1, 1);
        float r2 = __shfl_xor_sync(0xffffffffu, send2, 1);
        float gi, gf, gg, go;
        if (!odd) { gi = cc[0]; gf = cc[1]; gg = r1; go = r2; }
        else      { gi = r1;    gf = r2;    gg = cc[2]; go = cc[3]; }

        const int j = ((n0 + wn * 32 + nt * 8) >> 2) + ((l & 3) >> 1);
        const float4 b4 = *(const float4*)(P.bias + 4 * j);
        gi += b4.x; gf += b4.y; gg += b4.z; go += b4.w;

        const int bglob = m0 + wm * 16 + (l >> 2) + (odd ? 8 : 0);
        const int ix = bglob * HID + j;
        float cp = P.cbuf[ix];
        float cn = sigf(gf) * cp + sigf(gi) * tanhf(gg);
        float hn = sigf(go) * tanhf(cn);
        P.cbuf[ix] = cn;
        P.hOut[((size_t)(j >> 6) * BATCH + bglob) * 64 + swz(j & 63, bglob)] =
            __float2half(hn);
        if (P.hOutF != nullptr) P.hOutF[ix] = hn;
    }
}

// ---------------- FC head (+ next decode-input packing, swizzled) ----------------
__global__ void fc_head(const float* __restrict__ h1f,
                        const float* __restrict__ fcw, const float* __restrict__ fcb,
                        float* __restrict__ outp, const float* __restrict__ tf) {
    int idx = blockIdx.x * blockDim.x + threadIdx.x;   // 4096 = B*OUT
    int b = idx >> 3, o = idx & 7;
    const float4* h4 = (const float4*)(h1f + (size_t)b * HID);
    const float4* w4 = (const float4*)(fcw + (size_t)o * HID);
    float s = fcb[o];
#pragma unroll 4
    for (int j = 0; j < HID / 4; ++j) {
        float4 a = h4[j], wv = w4[j];
        s += a.x * wv.x + a.y * wv.y + a.z * wv.z + a.w * wv.w;
    }
    outp[b * OUT_DIM + o] = s;
    if (tf != nullptr) {
        g_ip[(size_t)b * 64 + swz(o, b)] = __float2half(s);
#pragma unroll
        for (int m = 0; m < 3; ++m) {
            int kk = 8 + o * 3 + m;
            g_ip[(size_t)b * 64 + swz(kk, b)] =
                __float2half(tf[(size_t)b * TF_DIM + o * 3 + m]);
        }
    }
}

// ---------------- host orchestration ----------------
extern "C" void kernel_launch(void* const* d_in, const int* in_sizes, int n_in,
                              void* d_out, int out_size) {
    const float* x     = (const float*)d_in[0];
    const float* ft    = (const float*)d_in[1];
    const float* h0in  = (const float*)d_in[2];
    const float* c0in  = (const float*)d_in[3];
    const float* w_ih0 = (const float*)d_in[4];
    const float* w_hh0 = (const float*)d_in[5];
    const float* b_ih0 = (const float*)d_in[6];
    const float* b_hh0 = (const float*)d_in[7];
    const float* w_ih1 = (const float*)d_in[8];
    const float* w_hh1 = (const float*)d_in[9];
    const float* b_ih1 = (const float*)d_in[10];
    const float* b_hh1 = (const float*)d_in[11];
    const float* fcw   = (const float*)d_in[12];
    const float* fcb   = (const float*)d_in[13];
    float* out = (float*)d_out;

    cudaFuncSetAttribute(lstm_cell, cudaFuncAttributeMaxDynamicSharedMemorySize, SMEM_B);

    __half *w0p, *w1p, *xp, *ip, *h0p, *h1p;
    float *h1fp, *c0p, *c1p, *b0p, *b1p;
    cudaGetSymbolAddress((void**)&w0p, g_w0);
    cudaGetSymbolAddress((void**)&w1p, g_w1);
    cudaGetSymbolAddress((void**)&xp, g_xp);
    cudaGetSymbolAddress((void**)&ip, g_ip);
    cudaGetSymbolAddress((void**)&h0p, g_h0);
    cudaGetSymbolAddress((void**)&h1p, g_h1);
    cudaGetSymbolAddress((void**)&h1fp, g_h1f);
    cudaGetSymbolAddress((void**)&c0p, g_c0);
    cudaGetSymbolAddress((void**)&c1p, g_c1);
    cudaGetSymbolAddress((void**)&b0p, g_b0);
    cudaGetSymbolAddress((void**)&b1p, g_b1);

    prep_w0<<<(G4 * KTOT0 + 255) / 256, 256>>>(w_ih0, w_hh0);
    prep_w1<<<(G4 * KTOT1 + 255) / 256, 256>>>(w_ih1, w_hh1);
    prep_bias<<<(G4 + 255) / 256, 256>>>(b_ih0, b_hh0, b_ih1, b_hh1);
    prep_xpad<<<(SEQ * BATCH * 64 + 255) / 256, 256>>>(x);
    prep_ipzero<<<(BATCH * 64 + 255) / 256, 256>>>();
    init_state<<<(BATCH * HID + 255) / 256, 256>>>(h0in, c0in);

    const int SN = BATCH * HID;
    CellP Z = {};

    auto mk_l0enc = [&](int s) {    // reads h0 buf s&1 + x[s]; writes buf (s+1)&1
        CellP a = {};
        a.slab0 = xp + (size_t)s * BATCH * 64;
        a.a1 = h0p + (size_t)(s & 1) * SN;
        a.wt = w0p; a.nch = NCH0;
        a.bias = b0p; a.cbuf = c0p;
        a.hOut = h0p + (size_t)((s + 1) & 1) * SN;
        return a;
    };
    auto mk_l0dec = [&](int s) {    // decode: chunk0 = g_ip
        CellP a = {};
        a.slab0 = ip;
        a.a1 = h0p + (size_t)(s & 1) * SN;
        a.wt = w0p; a.nch = NCH0;
        a.bias = b0p; a.cbuf = c0p;
        a.hOut = h0p + (size_t)((s + 1) & 1) * SN;
        return a;
    };
    auto mk_l1 = [&](int s, bool wf) {  // reads h0 buf (s+1)&1, h1 buf s&1
        CellP a = {};
        a.a1 = h0p + (size_t)((s + 1) & 1) * SN;
        a.a2 = h1p + (size_t)(s & 1) * SN;
        a.wt = w1p; a.nch = NCH1;
        a.bias = b1p; a.cbuf = c1p;
        a.hOut = h1p + (size_t)((s + 1) & 1) * SN;
        a.hOutF = wf ? h1fp : nullptr;
        return a;
    };

    const dim3 gridS(16, 8, 1), gridC(16, 8, 2);

    // encoder: pair l1(t) with independent l0(t+1)
    lstm_cell<<<gridS, THREADS, SMEM_B>>>(mk_l0enc(0), Z);
    for (int t = 0; t < SEQ - 1; ++t)
        lstm_cell<<<gridC, THREADS, SMEM_B>>>(mk_l1(t, false), mk_l0enc(t + 1));
    lstm_cell<<<gridS, THREADS, SMEM_B>>>(mk_l1(SEQ - 1, true), Z);

    fc_head<<<16, 256>>>(h1fp, fcw, fcb, out, ft);

    // autoregressive decode (r8 structure)
    for (int d = 0; d < FUT - 1; ++d) {
        lstm_cell<<<gridS, THREADS, SMEM_B>>>(mk_l0dec(SEQ + d), Z);
        lstm_cell<<<gridS, THREADS, SMEM_B>>>(mk_l1(SEQ + d, true), Z);
        fc_head<<<16, 256>>>(h1fp, fcw, fcb,
                             out + (size_t)(d + 1) * BATCH * OUT_DIM,
                             (d + 1 < FUT - 1) ? (ft + (size_t)(d + 1) * BATCH * TF_DIM)
                                               : nullptr);
    }
}

// round 12
// speedup vs baseline: 1.3222x; 1.0016x over previous
#include <cuda_runtime.h>
#include <cuda_fp16.h>
#include <cstdint>

#define HID 512
#define BATCH 512
#define G4 2048
#define NCH0 9
#define NCH1 16
#define SEQ 128
#define FUT 48
#define TF_DIM 24
#define OUT_DIM 8

#define THREADS 512
#define A_TILE_B 8192
#define B_TILE_B 16384
#define SLOT_B (2 * A_TILE_B + 2 * B_TILE_B)   // 49152: [A0|A1|B0B1]
#define MBAR_OFF (3 * SLOT_B)                  // 147456
#define SMEM_B (MBAR_OFF + 64)
#define CHSLAB 65536                           // bytes per (chunk, full-batch) A slab

// ---------------- persistent device buffers (chunk-tiled, pre-swizzled) ----------
__device__ __align__(256) __half g_w0[16 * NCH0 * 128 * 64];
__device__ __align__(256) __half g_w1[16 * NCH1 * 128 * 64];
__device__ __align__(256) __half g_xp[SEQ * BATCH * 64];
__device__ __align__(256) __half g_ip[BATCH * 64];
__device__ __align__(256) __half g_h0[2][BATCH * HID];
__device__ __align__(256) __half g_h1[2][BATCH * HID];
__device__ __align__(256) float g_h1f[BATCH * HID];
__device__ __align__(256) float g_pg[128 * 512 * 16];   // partial gates, 4MB
__device__ __align__(256) float g_c0[BATCH * HID];
__device__ __align__(256) float g_c1[BATCH * HID];
__device__ __align__(256) float g_b0[G4];
__device__ __align__(256) float g_b1[G4];

// ---------------- helpers ----------------
__device__ __forceinline__ int swz(int k, int r) {
    return (((k >> 3) ^ (r & 7)) << 3) | (k & 7);
}
__device__ __forceinline__ uint32_t smem_u32(const void* p) {
    uint32_t a;
    asm("{ .reg .u64 t; cvta.to.shared.u64 t, %1; cvt.u32.u64 %0, t; }" : "=r"(a) : "l"(p));
    return a;
}
__device__ __forceinline__ void cpbulk(uint32_t dst, const void* src, uint32_t bytes,
                                       uint32_t mbar) {
    asm volatile(
        "cp.async.bulk.shared::cluster.global.mbarrier::complete_tx::bytes "
        "[%0], [%1], %2, [%3];"
        :: "r"(dst), "l"(src), "r"(bytes), "r"(mbar) : "memory");
}
#define FENCE_ASYNC() asm volatile("fence.proxy.async.shared::cta;" ::: "memory")
#define MBAR_INIT(a, n) asm volatile("mbarrier.init.shared.b64 [%0], %1;" :: "r"(a), "r"(n) : "memory")
#define MBAR_EXPECT_TX(a, tx) asm volatile("mbarrier.arrive.expect_tx.shared.b64 _, [%0], %1;" :: "r"(a), "r"(tx) : "memory")

__device__ __forceinline__ void mbar_wait(uint32_t mbar, uint32_t parity) {
    asm volatile(
        "{\n\t.reg .pred P1;\n\t"
        "WL_%=:\n\t"
        "mbarrier.try_wait.parity.acquire.cta.shared::cta.b64 P1, [%0], %1, 0x989680;\n\t"
        "@P1 bra.uni WD_%=;\n\t"
        "bra.uni WL_%=;\n\t"
        "WD_%=:\n\t}"
        :: "r"(mbar), "r"(parity) : "memory");
}
__device__ __forceinline__ void ldsm4(uint32_t* r, uint32_t addr) {
    asm volatile("ldmatrix.sync.aligned.m8n8.x4.shared.b16 {%0,%1,%2,%3}, [%4];"
                 : "=r"(r[0]), "=r"(r[1]), "=r"(r[2]), "=r"(r[3]) : "r"(addr));
}
__device__ __forceinline__ void mma16816h(uint32_t* d, const uint32_t* a,
                                          const uint32_t* b) {
    asm volatile(
        "mma.sync.aligned.m16n8k16.row.col.f16.f16.f16.f16 "
        "{%0,%1}, {%2,%3,%4,%5}, {%6,%7}, {%0,%1};"
        : "+r"(d[0]), "+r"(d[1])
        : "r"(a[0]), "r"(a[1]), "r"(a[2]), "r"(a[3]), "r"(b[0]), "r"(b[1]));
}
__device__ __forceinline__ float sigf(float x) { return 1.0f / (1.0f + __expf(-x)); }

// ---------------- prep kernels (3 launches so ncu captures lstm_cell) -----------
__global__ void prep_w0(const float* __restrict__ wih, const float* __restrict__ whh) {
    int idx = blockIdx.x * blockDim.x + threadIdx.x;
    if (idx >= G4 * (64 + HID)) return;
    int n = idx / (64 + HID), k = idx - n * (64 + HID);
    int row = (n & 3) * HID + (n >> 2);
    float v;
    if (k < 64) v = (k < 32) ? wih[row * 32 + k] : 0.0f;
    else        v = whh[row * HID + (k - 64)];
    int r = n & 127;
    size_t dst = ((size_t)((n >> 7) * NCH0 + (k >> 6)) * 128 + r) * 64 + swz(k & 63, r);
    g_w0[dst] = __float2half(v);
}
__global__ void prep_w1(const float* __restrict__ wih, const float* __restrict__ whh) {
    int idx = blockIdx.x * blockDim.x + threadIdx.x;
    if (idx >= G4 * 1024) return;
    int n = idx >> 10, k = idx & 1023;
    int row = (n & 3) * HID + (n >> 2);
    float v = (k < HID) ? wih[row * HID + k] : whh[row * HID + (k - HID)];
    int r = n & 127;
    size_t dst = ((size_t)((n >> 7) * NCH1 + (k >> 6)) * 128 + r) * 64 + swz(k & 63, r);
    g_w1[dst] = __float2half(v);
}
__global__ void prep_misc(const float* __restrict__ x,
                          const float* __restrict__ h0in, const float* __restrict__ c0in,
                          const float* __restrict__ bi0, const float* __restrict__ bh0,
                          const float* __restrict__ bi1, const float* __restrict__ bh1) {
    int idx = blockIdx.x * blockDim.x + threadIdx.x;
    if (idx < SEQ * BATCH * 64) {   // xpad
        int k = idx & 63, b = (idx >> 6) & 511, t = idx >> 15;
        float v = (k < 32) ? x[((size_t)t * BATCH + b) * 32 + k] : 0.0f;
        g_xp[((size_t)t * BATCH + b) * 64 + swz(k, b)] = __float2half(v);
    }
    if (idx < BATCH * 64) g_ip[idx] = __float2half(0.0f);
    if (idx < G4) {
        int row = (idx & 3) * HID + (idx >> 2);
        g_b0[idx] = bi0[row] + bh0[row];
        g_b1[idx] = bi1[row] + bh1[row];
    }
    if (idx < BATCH * HID) {
        int b = idx >> 9, j = idx & (HID - 1);
        size_t dst = ((size_t)(j >> 6) * BATCH + b) * 64 + swz(j & 63, b);
        g_h0[0][dst] = __float2half(h0in[j]);
        g_h1[0][dst] = __float2half(h0in[HID + j]);
        g_c0[idx] = c0in[j];
        g_c1[idx] = c0in[HID + j];
    }
}

// ---------------- cell parameters ----------------
struct CellP {
    const __half* slab0;    // chunk0 A slab (xp row / g_ip) or null
    const __half* a1;       // h chunks (local 0..7 after slab0)
    const __half* a2;       // h chunks local 8..15 (encoder l1)
    const __half* wt;       // weight tile base
    int nch, woff, wstride; // chunks, weight tile offset, per-nblock tile stride
    const float* bias;
    float* cbuf;
    __half* hOut;
    float* hOutF;
    float* pgOut;           // l1a: write raw partial gates, skip LSTM epilogue
    const float* pgIn;      // l1b: add partial gates before epilogue
};

// ---------------- fused LSTM cell (16 warps, 64x128 tile, 128-K slots) ----------
__global__ __launch_bounds__(THREADS, 1)
void lstm_cell(CellP A0, CellP A1)
{
    const CellP P = blockIdx.z ? A1 : A0;
    extern __shared__ char smem_raw[];
    const uint32_t sb = smem_u32(smem_raw);
    const uint32_t mb = sb + MBAR_OFF;
    const int tid = threadIdx.x;
    const int l = tid & 31, w = tid >> 5;
    const int wm = w & 3;          // 0..3 : 16-row slab
    const int wn = w >> 2;         // 0..3 : 32-col slab
    const int n0 = blockIdx.x * 128;
    const int m0 = blockIdx.y * 64;
    const int nch = P.nch;
    const int nslots = (nch + 1) >> 1;

    if (tid == 0) {
#pragma unroll
        for (int s = 0; s < 3; ++s) MBAR_INIT(mb + s * 8, 1);
    }
    __syncthreads();

    const char* wbase = (const char*)P.wt +
        ((size_t)blockIdx.x * P.wstride + P.woff) * B_TILE_B;

    auto srcA = [&](int c) -> const char* {
        if (c == 0 && P.slab0 != nullptr)
            return (const char*)P.slab0 + (size_t)m0 * 128;
        int s1 = c - (P.slab0 != nullptr ? 1 : 0);
        const __half* base = (s1 < 8) ? P.a1 : P.a2;
        if (s1 >= 8) s1 -= 8;
        return (const char*)base + (size_t)s1 * CHSLAB + (size_t)m0 * 128;
    };

    auto issue = [&](int slot) {
        const int c0 = 2 * slot;
        const bool has2 = (c0 + 1 < nch);
        const uint32_t st = sb + (uint32_t)(slot % 3) * SLOT_B;
        const uint32_t m = mb + (uint32_t)(slot % 3) * 8;
        FENCE_ASYNC();
        MBAR_EXPECT_TX(m, (has2 ? 2u : 1u) * (A_TILE_B + B_TILE_B));
        cpbulk(st, srcA(c0), A_TILE_B, m);
        if (has2) cpbulk(st + A_TILE_B, srcA(c0 + 1), A_TILE_B, m);
        cpbulk(st + 2 * A_TILE_B, wbase + (size_t)c0 * B_TILE_B,
               (has2 ? 2u : 1u) * B_TILE_B, m);
    };

    if (tid == 0) { issue(0); if (nslots > 1) issue(1); }

    float acc[4][4];
#pragma unroll
    for (int nt = 0; nt < 4; ++nt)
#pragma unroll
        for (int i = 0; i < 4; ++i) acc[nt][i] = 0.0f;

    const uint32_t aRow = (uint32_t)(wm * 16 + (l & 15));
    const uint32_t aQl = (uint32_t)(l >> 4);
    const uint32_t bRowB = (uint32_t)(wn * 32 + (l & 7) + ((l >> 4) & 1) * 8);
    const uint32_t bQl = (uint32_t)((l >> 3) & 1);

    auto chunk_mma = [&](uint32_t aB, uint32_t bB) {
        uint32_t d16[4][2];
#pragma unroll
        for (int nt = 0; nt < 4; ++nt) { d16[nt][0] = 0u; d16[nt][1] = 0u; }
#pragma unroll
        for (int ks = 0; ks < 4; ++ks) {
            const uint32_t qa = aQl + ks * 2;
            uint32_t a[4];
            ldsm4(a, aB + aRow * 128 + ((qa ^ (aRow & 7)) << 4));
            uint32_t b[4][2];
#pragma unroll
            for (int ntp = 0; ntp < 2; ++ntp) {
                const uint32_t br = bRowB + ntp * 16;
                const uint32_t qb = bQl + ks * 2;
                uint32_t r4[4];
                ldsm4(r4, bB + br * 128 + ((qb ^ (br & 7)) << 4));
                b[ntp * 2][0] = r4[0]; b[ntp * 2][1] = r4[1];
                b[ntp * 2 + 1][0] = r4[2]; b[ntp * 2 + 1][1] = r4[3];
            }
#pragma unroll
            for (int nt = 0; nt < 4; ++nt)
                mma16816h(d16[nt], a, b[nt]);
        }
#pragma unroll
        for (int nt = 0; nt < 4; ++nt) {
            float2 p0 = __half22float2(*(const __half2*)&d16[nt][0]);
            float2 p1 = __half22float2(*(const __half2*)&d16[nt][1]);
            acc[nt][0] += p0.x; acc[nt][1] += p0.y;
            acc[nt][2] += p1.x; acc[nt][3] += p1.y;
        }
    };

    for (int slot = 0; slot < nslots; ++slot) {
        if (slot > 0) __syncthreads();
        if (tid == 0 && slot + 2 < nslots) issue(slot + 2);
        mbar_wait(mb + (uint32_t)(slot % 3) * 8, (uint32_t)((slot / 3) & 1));
        const uint32_t stage = sb + (uint32_t)(slot % 3) * SLOT_B;
        chunk_mma(stage, stage + 2 * A_TILE_B);
        if (2 * slot + 1 < nch)
            chunk_mma(stage + A_TILE_B, stage + 2 * A_TILE_B + B_TILE_B);
    }

    // ---- partial-gate write path (l1a): raw acc out, no epilogue ----
    const size_t pgbase =
        (((size_t)blockIdx.x * 8 + blockIdx.y) * THREADS + tid) * 16;
    if (P.pgOut != nullptr) {
#pragma unroll
        for (int nt = 0; nt < 4; ++nt)
            *(float4*)(P.pgOut + pgbase + nt * 4) =
                make_float4(acc[nt][0], acc[nt][1], acc[nt][2], acc[nt][3]);
        return;
    }

    // ---- epilogue: optional partial add, gate assembly, LSTM update ----
    const bool odd = (l & 1) != 0;
#pragma unroll
    for (int nt = 0; nt < 4; ++nt) {
        float* cc = acc[nt];
        if (P.pgIn != nullptr) {
            float4 pg = *(const float4*)(P.pgIn + pgbase + nt * 4);
            cc[0] += pg.x; cc[1] += pg.y; cc[2] += pg.z; cc[3] += pg.w;
        }
        float send1 = odd ? cc[0] : cc[2];
        float send2 = odd ? cc[1] : cc[3];
        float r1 = __shfl_xor_sync(0xffffffffu, send1, 1);
        float r2 = __shfl_xor_sync(0xffffffffu, send2, 1);
        float gi, gf, gg, go;
        if (!odd) { gi = cc[0]; gf = cc[1]; gg = r1; go = r2; }
        else      { gi = r1;    gf = r2;    gg = cc[2]; go = cc[3]; }

        const int j = ((n0 + wn * 32 + nt * 8) >> 2) + ((l & 3) >> 1);
        const float4 b4 = *(const float4*)(P.bias + 4 * j);
        gi += b4.x; gf += b4.y; gg += b4.z; go += b4.w;

        const int bglob = m0 + wm * 16 + (l >> 2) + (odd ? 8 : 0);
        const int ix = bglob * HID + j;
        float cp = P.cbuf[ix];
        float cn = sigf(gf) * cp + sigf(gi) * tanhf(gg);
        float hn = sigf(go) * tanhf(cn);
        P.cbuf[ix] = cn;
        P.hOut[((size_t)(j >> 6) * BATCH + bglob) * 64 + swz(j & 63, bglob)] =
            __float2half(hn);
        if (P.hOutF != nullptr) P.hOutF[ix] = hn;
    }
}

// ---------------- FC head (+ next decode-input packing, swizzled) ----------------
__global__ void fc_head(const float* __restrict__ h1f,
                        const float* __restrict__ fcw, const float* __restrict__ fcb,
                        float* __restrict__ outp, const float* __restrict__ tf) {
    int idx = blockIdx.x * blockDim.x + threadIdx.x;   // 4096 = B*OUT
    int b = idx >> 3, o = idx & 7;
    const float4* h4 = (const float4*)(h1f + (size_t)b * HID);
    const float4* w4 = (const float4*)(fcw + (size_t)o * HID);
    float s = fcb[o];
#pragma unroll 4
    for (int j = 0; j < HID / 4; ++j) {
        float4 a = h4[j], wv = w4[j];
        s += a.x * wv.x + a.y * wv.y + a.z * wv.z + a.w * wv.w;
    }
    outp[b * OUT_DIM + o] = s;
    if (tf != nullptr) {
        g_ip[(size_t)b * 64 + swz(o, b)] = __float2half(s);
#pragma unroll
        for (int m = 0; m < 3; ++m) {
            int kk = 8 + o * 3 + m;
            g_ip[(size_t)b * 64 + swz(kk, b)] =
                __float2half(tf[(size_t)b * TF_DIM + o * 3 + m]);
        }
    }
}

// ---------------- host orchestration ----------------
extern "C" void kernel_launch(void* const* d_in, const int* in_sizes, int n_in,
                              void* d_out, int out_size) {
    const float* x     = (const float*)d_in[0];
    const float* ft    = (const float*)d_in[1];
    const float* h0in  = (const float*)d_in[2];
    const float* c0in  = (const float*)d_in[3];
    const float* w_ih0 = (const float*)d_in[4];
    const float* w_hh0 = (const float*)d_in[5];
    const float* b_ih0 = (const float*)d_in[6];
    const float* b_hh0 = (const float*)d_in[7];
    const float* w_ih1 = (const float*)d_in[8];
    const float* w_hh1 = (const float*)d_in[9];
    const float* b_ih1 = (const float*)d_in[10];
    const float* b_hh1 = (const float*)d_in[11];
    const float* fcw   = (const float*)d_in[12];
    const float* fcb   = (const float*)d_in[13];
    float* out = (float*)d_out;

    cudaFuncSetAttribute(lstm_cell, cudaFuncAttributeMaxDynamicSharedMemorySize, SMEM_B);

    __half *w0p, *w1p, *xp, *ip, *h0p, *h1p;
    float *h1fp, *pgp, *c0p, *c1p, *b0p, *b1p;
    cudaGetSymbolAddress((void**)&w0p, g_w0);
    cudaGetSymbolAddress((void**)&w1p, g_w1);
    cudaGetSymbolAddress((void**)&xp, g_xp);
    cudaGetSymbolAddress((void**)&ip, g_ip);
    cudaGetSymbolAddress((void**)&h0p, g_h0);
    cudaGetSymbolAddress((void**)&h1p, g_h1);
    cudaGetSymbolAddress((void**)&h1fp, g_h1f);
    cudaGetSymbolAddress((void**)&pgp, g_pg);
    cudaGetSymbolAddress((void**)&c0p, g_c0);
    cudaGetSymbolAddress((void**)&c1p, g_c1);
    cudaGetSymbolAddress((void**)&b0p, g_b0);
    cudaGetSymbolAddress((void**)&b1p, g_b1);

    prep_w0<<<(G4 * (64 + HID) + 255) / 256, 256>>>(w_ih0, w_hh0);
    prep_w1<<<(G4 * 1024 + 255) / 256, 256>>>(w_ih1, w_hh1);
    prep_misc<<<(SEQ * BATCH * 64 + 255) / 256, 256>>>(x, h0in, c0in,
                                                       b_ih0, b_hh0, b_ih1, b_hh1);

    const int SN = BATCH * HID;
    CellP Z = {};

    auto mk_l0 = [&](int s, const __half* slab) {
        CellP a = {};
        a.slab0 = slab;
        a.a1 = h0p + (size_t)(s & 1) * SN;
        a.wt = w0p; a.nch = NCH0; a.woff = 0; a.wstride = NCH0;
        a.bias = b0p; a.cbuf = c0p;
        a.hOut = h0p + (size_t)((s + 1) & 1) * SN;
        return a;
    };
    auto mk_l1full = [&](int s, bool wf) {
        CellP a = {};
        a.a1 = h0p + (size_t)((s + 1) & 1) * SN;
        a.a2 = h1p + (size_t)(s & 1) * SN;
        a.wt = w1p; a.nch = NCH1; a.woff = 0; a.wstride = NCH1;
        a.bias = b1p; a.cbuf = c1p;
        a.hOut = h1p + (size_t)((s + 1) & 1) * SN;
        a.hOutF = wf ? h1fp : nullptr;
        return a;
    };
    auto mk_l1a = [&](int s) {   // h1_old half (weight chunks 8..15) -> partial gates
        CellP a = {};
        a.a1 = h1p + (size_t)(s & 1) * SN;
        a.wt = w1p; a.nch = 8; a.woff = 8; a.wstride = NCH1;
        a.pgOut = pgp;
        return a;
    };
    auto mk_l1b = [&](int s) {   // h0_new half (weight chunks 0..7) + partial add
        CellP a = {};
        a.a1 = h0p + (size_t)((s + 1) & 1) * SN;
        a.wt = w1p; a.nch = 8; a.woff = 0; a.wstride = NCH1;
        a.pgIn = pgp;
        a.bias = b1p; a.cbuf = c1p;
        a.hOut = h1p + (size_t)((s + 1) & 1) * SN;
        a.hOutF = h1fp;
        return a;
    };

    const dim3 gridS(16, 8, 1), gridC(16, 8, 2);

    // encoder: pair l1(t) with independent l0(t+1)
    lstm_cell<<<gridS, THREADS, SMEM_B>>>(mk_l0(0, xp), Z);
    for (int t = 0; t < SEQ - 1; ++t)
        lstm_cell<<<gridC, THREADS, SMEM_B>>>(mk_l1full(t, false),
                                              mk_l0(t + 1, xp + (size_t)(t + 1) * BATCH * 64));
    lstm_cell<<<gridS, THREADS, SMEM_B>>>(mk_l1full(SEQ - 1, true), Z);

    fc_head<<<16, 256>>>(h1fp, fcw, fcb, out, ft);

    // autoregressive decode: pair l0dec(d) with l1a(d); l1b finishes
    for (int d = 0; d < FUT - 1; ++d) {
        const int s = SEQ + d;
        lstm_cell<<<gridC, THREADS, SMEM_B>>>(mk_l0(s, ip), mk_l1a(s));
        lstm_cell<<<gridS, THREADS, SMEM_B>>>(mk_l1b(s), Z);
        fc_head<<<16, 256>>>(h1fp, fcw, fcb,
                             out + (size_t)(d + 1) * BATCH * OUT_DIM,
                             (d + 1 < FUT - 1) ? (ft + (size_t)(d + 1) * BATCH * TF_DIM)
                                               : nullptr);
    }
}

// round 13
// speedup vs baseline: 1.3574x; 1.0266x over previous
#include <cuda_runtime.h>
#include <cuda_fp16.h>
#include <cstdint>

#define HID 512
#define BATCH 512
#define G4 2048
#define NCH0 9
#define NCH1 16
#define SEQ 128
#define FUT 48
#define TF_DIM 24
#define OUT_DIM 8

#define THREADS 512
#define A_TILE_B 8192
#define B_TILE_B 16384
#define SLOT_B (2 * A_TILE_B + 2 * B_TILE_B)   // 49152: [A0|A1|B0B1]
#define MBAR_OFF (3 * SLOT_B)                  // 147456
#define SMEM_B (MBAR_OFF + 64)
#define CHSLAB 65536                           // bytes per (chunk, full-batch) A slab

// ---------------- persistent device buffers (chunk-tiled, pre-swizzled) ----------
__device__ __align__(256) __half g_w0[16 * NCH0 * 128 * 64];
__device__ __align__(256) __half g_w1[16 * NCH1 * 128 * 64];
__device__ __align__(256) __half g_xp[SEQ * BATCH * 64];
__device__ __align__(256) __half g_ip[BATCH * 64];
__device__ __align__(256) __half g_h0[2][BATCH * HID];
__device__ __align__(256) __half g_h1[2][BATCH * HID];
__device__ __align__(256) float g_h1f[BATCH * HID];
__device__ __align__(256) float g_pg[128 * 512 * 16];   // partial gates, 4MB
__device__ __align__(256) float g_c0[BATCH * HID];
__device__ __align__(256) float g_c1[BATCH * HID];
__device__ __align__(256) float g_b0[G4];
__device__ __align__(256) float g_b1[G4];

// ---------------- helpers ----------------
__device__ __forceinline__ int swz(int k, int r) {
    return (((k >> 3) ^ (r & 7)) << 3) | (k & 7);
}
__device__ __forceinline__ uint32_t smem_u32(const void* p) {
    uint32_t a;
    asm("{ .reg .u64 t; cvta.to.shared.u64 t, %1; cvt.u32.u64 %0, t; }" : "=r"(a) : "l"(p));
    return a;
}
__device__ __forceinline__ void cpbulk(uint32_t dst, const void* src, uint32_t bytes,
                                       uint32_t mbar) {
    asm volatile(
        "cp.async.bulk.shared::cluster.global.mbarrier::complete_tx::bytes "
        "[%0], [%1], %2, [%3];"
        :: "r"(dst), "l"(src), "r"(bytes), "r"(mbar) : "memory");
}
#define FENCE_ASYNC() asm volatile("fence.proxy.async.shared::cta;" ::: "memory")
#define MBAR_INIT(a, n) asm volatile("mbarrier.init.shared.b64 [%0], %1;" :: "r"(a), "r"(n) : "memory")
#define MBAR_EXPECT_TX(a, tx) asm volatile("mbarrier.arrive.expect_tx.shared.b64 _, [%0], %1;" :: "r"(a), "r"(tx) : "memory")
#define MBAR_ARRIVE(a) asm volatile("mbarrier.arrive.shared.b64 _, [%0];" :: "r"(a) : "memory")

__device__ __forceinline__ void mbar_wait(uint32_t mbar, uint32_t parity) {
    asm volatile(
        "{\n\t.reg .pred P1;\n\t"
        "WL_%=:\n\t"
        "mbarrier.try_wait.parity.acquire.cta.shared::cta.b64 P1, [%0], %1, 0x989680;\n\t"
        "@P1 bra.uni WD_%=;\n\t"
        "bra.uni WL_%=;\n\t"
        "WD_%=:\n\t}"
        :: "r"(mbar), "r"(parity) : "memory");
}
__device__ __forceinline__ void ldsm4(uint32_t* r, uint32_t addr) {
    asm volatile("ldmatrix.sync.aligned.m8n8.x4.shared.b16 {%0,%1,%2,%3}, [%4];"
                 : "=r"(r[0]), "=r"(r[1]), "=r"(r[2]), "=r"(r[3]) : "r"(addr));
}
__device__ __forceinline__ void mma16816h(uint32_t* d, const uint32_t* a,
                                          const uint32_t* b) {
    asm volatile(
        "mma.sync.aligned.m16n8k16.row.col.f16.f16.f16.f16 "
        "{%0,%1}, {%2,%3,%4,%5}, {%6,%7}, {%0,%1};"
        : "+r"(d[0]), "+r"(d[1])
        : "r"(a[0]), "r"(a[1]), "r"(a[2]), "r"(a[3]), "r"(b[0]), "r"(b[1]));
}
__device__ __forceinline__ float sigf(float x) { return 1.0f / (1.0f + __expf(-x)); }

// ---------------- prep kernels ----------------
__global__ void prep_w0(const float* __restrict__ wih, const float* __restrict__ whh) {
    int idx = blockIdx.x * blockDim.x + threadIdx.x;
    if (idx >= G4 * (64 + HID)) return;
    int n = idx / (64 + HID), k = idx - n * (64 + HID);
    int row = (n & 3) * HID + (n >> 2);
    float v;
    if (k < 64) v = (k < 32) ? wih[row * 32 + k] : 0.0f;
    else        v = whh[row * HID + (k - 64)];
    int r = n & 127;
    size_t dst = ((size_t)((n >> 7) * NCH0 + (k >> 6)) * 128 + r) * 64 + swz(k & 63, r);
    g_w0[dst] = __float2half(v);
}
__global__ void prep_w1(const float* __restrict__ wih, const float* __restrict__ whh) {
    int idx = blockIdx.x * blockDim.x + threadIdx.x;
    if (idx >= G4 * 1024) return;
    int n = idx >> 10, k = idx & 1023;
    int row = (n & 3) * HID + (n >> 2);
    float v = (k < HID) ? wih[row * HID + k] : whh[row * HID + (k - HID)];
    int r = n & 127;
    size_t dst = ((size_t)((n >> 7) * NCH1 + (k >> 6)) * 128 + r) * 64 + swz(k & 63, r);
    g_w1[dst] = __float2half(v);
}
__global__ void prep_misc(const float* __restrict__ x,
                          const float* __restrict__ h0in, const float* __restrict__ c0in,
                          const float* __restrict__ bi0, const float* __restrict__ bh0,
                          const float* __restrict__ bi1, const float* __restrict__ bh1) {
    int idx = blockIdx.x * blockDim.x + threadIdx.x;
    if (idx < SEQ * BATCH * 64) {   // xpad
        int k = idx & 63, b = (idx >> 6) & 511, t = idx >> 15;
        float v = (k < 32) ? x[((size_t)t * BATCH + b) * 32 + k] : 0.0f;
        g_xp[((size_t)t * BATCH + b) * 64 + swz(k, b)] = __float2half(v);
    }
    if (idx < BATCH * 64) g_ip[idx] = __float2half(0.0f);
    if (idx < G4) {
        int row = (idx & 3) * HID + (idx >> 2);
        g_b0[idx] = bi0[row] + bh0[row];
        g_b1[idx] = bi1[row] + bh1[row];
    }
    if (idx < BATCH * HID) {
        int b = idx >> 9, j = idx & (HID - 1);
        size_t dst = ((size_t)(j >> 6) * BATCH + b) * 64 + swz(j & 63, b);
        g_h0[0][dst] = __float2half(h0in[j]);
        g_h1[0][dst] = __float2half(h0in[HID + j]);
        g_c0[idx] = c0in[j];
        g_c1[idx] = c0in[HID + j];
    }
}

// ---------------- cell parameters ----------------
struct CellP {
    const __half* slab0;    // chunk0 A slab (xp row / g_ip) or null
    const __half* a1;       // h chunks (local 0..7 after slab0)
    const __half* a2;       // h chunks local 8..15 (encoder l1)
    const __half* wt;       // weight tile base
    int nch, woff, wstride;
    const float* bias;
    float* cbuf;
    __half* hOut;
    float* hOutF;
    float* pgOut;           // l1a: write raw partial gates, skip LSTM epilogue
    const float* pgIn;      // l1b: add partial gates before epilogue
};

// ---------------- fused LSTM cell (16 warps, 128-K slots, mbar-only sync) -------
__global__ __launch_bounds__(THREADS, 1)
void lstm_cell(CellP A0, CellP A1)
{
    const CellP P = blockIdx.z ? A1 : A0;
    extern __shared__ char smem_raw[];
    const uint32_t sb = smem_u32(smem_raw);
    const uint32_t mb = sb + MBAR_OFF;          // full[0..2] @ +0,8,16 ; free[0..2] @ +24,32,40
    const int tid = threadIdx.x;
    const int l = tid & 31, w = tid >> 5;
    const int wm = w & 3;
    const int wn = w >> 2;
    const int n0 = blockIdx.x * 128;
    const int m0 = blockIdx.y * 64;
    const int nch = P.nch;
    const int nslots = (nch + 1) >> 1;

    if (tid == 0) {
#pragma unroll
        for (int s = 0; s < 3; ++s) MBAR_INIT(mb + s * 8, 1);       // full (tx)
#pragma unroll
        for (int s = 0; s < 3; ++s) MBAR_INIT(mb + 24 + s * 8, 16); // free (16 warps)
    }
    __syncthreads();

    const char* wbase = (const char*)P.wt +
        ((size_t)blockIdx.x * P.wstride + P.woff) * B_TILE_B;

    auto srcA = [&](int c) -> const char* {
        if (c == 0 && P.slab0 != nullptr)
            return (const char*)P.slab0 + (size_t)m0 * 128;
        int s1 = c - (P.slab0 != nullptr ? 1 : 0);
        const __half* base = (s1 < 8) ? P.a1 : P.a2;
        if (s1 >= 8) s1 -= 8;
        return (const char*)base + (size_t)s1 * CHSLAB + (size_t)m0 * 128;
    };

    auto issue = [&](int k) {
        if (k >= 3)   // ring slot reuse: wait until all 16 warps consumed slot k-3
            mbar_wait(mb + 24 + (uint32_t)(k % 3) * 8, (uint32_t)((k / 3 - 1) & 1));
        const int c0 = 2 * k;
        const bool has2 = (c0 + 1 < nch);
        const uint32_t st = sb + (uint32_t)(k % 3) * SLOT_B;
        const uint32_t m = mb + (uint32_t)(k % 3) * 8;
        FENCE_ASYNC();
        MBAR_EXPECT_TX(m, (has2 ? 2u : 1u) * (A_TILE_B + B_TILE_B));
        cpbulk(st, srcA(c0), A_TILE_B, m);
        if (has2) cpbulk(st + A_TILE_B, srcA(c0 + 1), A_TILE_B, m);
        cpbulk(st + 2 * A_TILE_B, wbase + (size_t)c0 * B_TILE_B,
               (has2 ? 2u : 1u) * B_TILE_B, m);
    };

    if (tid == 0) {
        issue(0);
        if (nslots > 1) issue(1);
        if (nslots > 2) issue(2);
    }

    float acc[4][4];
#pragma unroll
    for (int nt = 0; nt < 4; ++nt)
#pragma unroll
        for (int i = 0; i < 4; ++i) acc[nt][i] = 0.0f;

    const uint32_t aRow = (uint32_t)(wm * 16 + (l & 15));
    const uint32_t aQl = (uint32_t)(l >> 4);
    const uint32_t bRowB = (uint32_t)(wn * 32 + (l & 7) + ((l >> 4) & 1) * 8);
    const uint32_t bQl = (uint32_t)((l >> 3) & 1);

    auto chunk_mma = [&](uint32_t aB, uint32_t bB) {
        uint32_t d16[4][2];
#pragma unroll
        for (int nt = 0; nt < 4; ++nt) { d16[nt][0] = 0u; d16[nt][1] = 0u; }
#pragma unroll
        for (int ks = 0; ks < 4; ++ks) {
            const uint32_t qa = aQl + ks * 2;
            uint32_t a[4];
            ldsm4(a, aB + aRow * 128 + ((qa ^ (aRow & 7)) << 4));
            uint32_t b[4][2];
#pragma unroll
            for (int ntp = 0; ntp < 2; ++ntp) {
                const uint32_t br = bRowB + ntp * 16;
                const uint32_t qb = bQl + ks * 2;
                uint32_t r4[4];
                ldsm4(r4, bB + br * 128 + ((qb ^ (br & 7)) << 4));
                b[ntp * 2][0] = r4[0]; b[ntp * 2][1] = r4[1];
                b[ntp * 2 + 1][0] = r4[2]; b[ntp * 2 + 1][1] = r4[3];
            }
#pragma unroll
            for (int nt = 0; nt < 4; ++nt)
                mma16816h(d16[nt], a, b[nt]);
        }
#pragma unroll
        for (int nt = 0; nt < 4; ++nt) {
            float2 p0 = __half22float2(*(const __half2*)&d16[nt][0]);
            float2 p1 = __half22float2(*(const __half2*)&d16[nt][1]);
            acc[nt][0] += p0.x; acc[nt][1] += p0.y;
            acc[nt][2] += p1.x; acc[nt][3] += p1.y;
        }
    };

    for (int slot = 0; slot < nslots; ++slot) {
        mbar_wait(mb + (uint32_t)(slot % 3) * 8, (uint32_t)((slot / 3) & 1));
        const uint32_t stage = sb + (uint32_t)(slot % 3) * SLOT_B;
        chunk_mma(stage, stage + 2 * A_TILE_B);
        if (2 * slot + 1 < nch)
            chunk_mma(stage + A_TILE_B, stage + 2 * A_TILE_B + B_TILE_B);
        if (l == 0) MBAR_ARRIVE(mb + 24 + (uint32_t)(slot % 3) * 8);  // warp done with slot
        if (tid == 0 && slot + 3 < nslots) issue(slot + 3);
    }

    // ---- partial-gate write path (l1a) ----
    const size_t pgbase =
        (((size_t)blockIdx.x * 8 + blockIdx.y) * THREADS + tid) * 16;
    if (P.pgOut != nullptr) {
#pragma unroll
        for (int nt = 0; nt < 4; ++nt)
            *(float4*)(P.pgOut + pgbase + nt * 4) =
                make_float4(acc[nt][0], acc[nt][1], acc[nt][2], acc[nt][3]);
        return;
    }

    // ---- epilogue ----
    const bool odd = (l & 1) != 0;
#pragma unroll
    for (int nt = 0; nt < 4; ++nt) {
        float* cc = acc[nt];
        if (P.pgIn != nullptr) {
            float4 pg = *(const float4*)(P.pgIn + pgbase + nt * 4);
            cc[0] += pg.x; cc[1] += pg.y; cc[2] += pg.z; cc[3] += pg.w;
        }
        float send1 = odd ? cc[0] : cc[2];
        float send2 = odd ? cc[1] : cc[3];
        float r1 = __shfl_xor_sync(0xffffffffu, send1, 1);
        float r2 = __shfl_xor_sync(0xffffffffu, send2, 1);
        float gi, gf, gg, go;
        if (!odd) { gi = cc[0]; gf = cc[1]; gg = r1; go = r2; }
        else      { gi = r1;    gf = r2;    gg = cc[2]; go = cc[3]; }

        const int j = ((n0 + wn * 32 + nt * 8) >> 2) + ((l & 3) >> 1);
        const float4 b4 = *(const float4*)(P.bias + 4 * j);
        gi += b4.x; gf += b4.y; gg += b4.z; go += b4.w;

        const int bglob = m0 + wm * 16 + (l >> 2) + (odd ? 8 : 0);
        const int ix = bglob * HID + j;
        float cp = P.cbuf[ix];
        float cn = sigf(gf) * cp + sigf(gi) * tanhf(gg);
        float hn = sigf(go) * tanhf(cn);
        P.cbuf[ix] = cn;
        P.hOut[((size_t)(j >> 6) * BATCH + bglob) * 64 + swz(j & 63, bglob)] =
            __float2half(hn);
        if (P.hOutF != nullptr) P.hOutF[ix] = hn;
    }
}

// ---------------- FC head (+ next decode-input packing, swizzled) ----------------
__global__ void fc_head(const float* __restrict__ h1f,
                        const float* __restrict__ fcw, const float* __restrict__ fcb,
                        float* __restrict__ outp, const float* __restrict__ tf) {
    int idx = blockIdx.x * blockDim.x + threadIdx.x;   // 4096 = B*OUT
    int b = idx >> 3, o = idx & 7;
    const float4* h4 = (const float4*)(h1f + (size_t)b * HID);
    const float4* w4 = (const float4*)(fcw + (size_t)o * HID);
    float s = fcb[o];
#pragma unroll 4
    for (int j = 0; j < HID / 4; ++j) {
        float4 a = h4[j], wv = w4[j];
        s += a.x * wv.x + a.y * wv.y + a.z * wv.z + a.w * wv.w;
    }
    outp[b * OUT_DIM + o] = s;
    if (tf != nullptr) {
        g_ip[(size_t)b * 64 + swz(o, b)] = __float2half(s);
#pragma unroll
        for (int m = 0; m < 3; ++m) {
            int kk = 8 + o * 3 + m;
            g_ip[(size_t)b * 64 + swz(kk, b)] =
                __float2half(tf[(size_t)b * TF_DIM + o * 3 + m]);
        }
    }
}

// ---------------- host orchestration ----------------
extern "C" void kernel_launch(void* const* d_in, const int* in_sizes, int n_in,
                              void* d_out, int out_size) {
    const float* x     = (const float*)d_in[0];
    const float* ft    = (const float*)d_in[1];
    const float* h0in  = (const float*)d_in[2];
    const float* c0in  = (const float*)d_in[3];
    const float* w_ih0 = (const float*)d_in[4];
    const float* w_hh0 = (const float*)d_in[5];
    const float* b_ih0 = (const float*)d_in[6];
    const float* b_hh0 = (const float*)d_in[7];
    const float* w_ih1 = (const float*)d_in[8];
    const float* w_hh1 = (const float*)d_in[9];
    const float* b_ih1 = (const float*)d_in[10];
    const float* b_hh1 = (const float*)d_in[11];
    const float* fcw   = (const float*)d_in[12];
    const float* fcb   = (const float*)d_in[13];
    float* out = (float*)d_out;

    cudaFuncSetAttribute(lstm_cell, cudaFuncAttributeMaxDynamicSharedMemorySize, SMEM_B);

    __half *w0p, *w1p, *xp, *ip, *h0p, *h1p;
    float *h1fp, *pgp, *c0p, *c1p, *b0p, *b1p;
    cudaGetSymbolAddress((void**)&w0p, g_w0);
    cudaGetSymbolAddress((void**)&w1p, g_w1);
    cudaGetSymbolAddress((void**)&xp, g_xp);
    cudaGetSymbolAddress((void**)&ip, g_ip);
    cudaGetSymbolAddress((void**)&h0p, g_h0);
    cudaGetSymbolAddress((void**)&h1p, g_h1);
    cudaGetSymbolAddress((void**)&h1fp, g_h1f);
    cudaGetSymbolAddress((void**)&pgp, g_pg);
    cudaGetSymbolAddress((void**)&c0p, g_c0);
    cudaGetSymbolAddress((void**)&c1p, g_c1);
    cudaGetSymbolAddress((void**)&b0p, g_b0);
    cudaGetSymbolAddress((void**)&b1p, g_b1);

    prep_w0<<<(G4 * (64 + HID) + 255) / 256, 256>>>(w_ih0, w_hh0);
    prep_w1<<<(G4 * 1024 + 255) / 256, 256>>>(w_ih1, w_hh1);
    prep_misc<<<(SEQ * BATCH * 64 + 255) / 256, 256>>>(x, h0in, c0in,
                                                       b_ih0, b_hh0, b_ih1, b_hh1);

    const int SN = BATCH * HID;
    CellP Z = {};

    auto mk_l0 = [&](int s, const __half* slab) {
        CellP a = {};
        a.slab0 = slab;
        a.a1 = h0p + (size_t)(s & 1) * SN;
        a.wt = w0p; a.nch = NCH0; a.woff = 0; a.wstride = NCH0;
        a.bias = b0p; a.cbuf = c0p;
        a.hOut = h0p + (size_t)((s + 1) & 1) * SN;
        return a;
    };
    auto mk_l1full = [&](int s, bool wf) {
        CellP a = {};
        a.a1 = h0p + (size_t)((s + 1) & 1) * SN;
        a.a2 = h1p + (size_t)(s & 1) * SN;
        a.wt = w1p; a.nch = NCH1; a.woff = 0; a.wstride = NCH1;
        a.bias = b1p; a.cbuf = c1p;
        a.hOut = h1p + (size_t)((s + 1) & 1) * SN;
        a.hOutF = wf ? h1fp : nullptr;
        return a;
    };
    auto mk_l1a = [&](int s) {   // h1_old half -> partial gates
        CellP a = {};
        a.a1 = h1p + (size_t)(s & 1) * SN;
        a.wt = w1p; a.nch = 8; a.woff = 8; a.wstride = NCH1;
        a.pgOut = pgp;
        return a;
    };
    auto mk_l1b = [&](int s) {   // h0_new half + partial add
        CellP a = {};
        a.a1 = h0p + (size_t)((s + 1) & 1) * SN;
        a.wt = w1p; a.nch = 8; a.woff = 0; a.wstride = NCH1;
        a.pgIn = pgp;
        a.bias = b1p; a.cbuf = c1p;
        a.hOut = h1p + (size_t)((s + 1) & 1) * SN;
        a.hOutF = h1fp;
        return a;
    };

    const dim3 gridS(16, 8, 1), gridC(16, 8, 2);

    // encoder: pair l1(t) with independent l0(t+1)
    lstm_cell<<<gridS, THREADS, SMEM_B>>>(mk_l0(0, xp), Z);
    for (int t = 0; t < SEQ - 1; ++t)
        lstm_cell<<<gridC, THREADS, SMEM_B>>>(mk_l1full(t, false),
                                              mk_l0(t + 1, xp + (size_t)(t + 1) * BATCH * 64));
    lstm_cell<<<gridS, THREADS, SMEM_B>>>(mk_l1full(SEQ - 1, true), Z);

    fc_head<<<16, 256>>>(h1fp, fcw, fcb, out, ft);

    // autoregressive decode: pair l0dec(d) with l1a(d); l1b finishes
    for (int d = 0; d < FUT - 1; ++d) {
        const int s = SEQ + d;
        lstm_cell<<<gridC, THREADS, SMEM_B>>>(mk_l0(s, ip), mk_l1a(s));
        lstm_cell<<<gridS, THREADS, SMEM_B>>>(mk_l1b(s), Z);
        fc_head<<<16, 256>>>(h1fp, fcw, fcb,
                             out + (size_t)(d + 1) * BATCH * OUT_DIM,
                             (d + 1 < FUT - 1) ? (ft + (size_t)(d + 1) * BATCH * TF_DIM)
                                               : nullptr);
    }
}

// round 14
// speedup vs baseline: 1.5700x; 1.1566x over previous
#include <cuda_runtime.h>
#include <cuda_fp16.h>
#include <cstdint>

#define HID 512
#define BATCH 512
#define G4 2048
#define NCH0 9
#define NCH1 16
#define SEQ 128
#define FUT 48
#define TF_DIM 24
#define OUT_DIM 8

#define THREADS 512
#define A_TILE_B 8192
#define B_TILE_B 16384
#define SLOT_B (2 * A_TILE_B + 2 * B_TILE_B)   // 49152: [A0|A1|B0B1]
#define MBAR_OFF (2 * SLOT_B)                  // 98304  (2-slot ring)
#define SMEM_B (MBAR_OFF + 64)                 // 98368 -> 2 CTAs/SM
#define CHSLAB 65536                           // bytes per (chunk, full-batch) A slab

// ---------------- persistent device buffers (chunk-tiled, pre-swizzled) ----------
__device__ __align__(256) __half g_w0[16 * NCH0 * 128 * 64];
__device__ __align__(256) __half g_w1[16 * NCH1 * 128 * 64];
__device__ __align__(256) __half g_xp[SEQ * BATCH * 64];
__device__ __align__(256) __half g_ip[BATCH * 64];
__device__ __align__(256) __half g_h0[2][BATCH * HID];
__device__ __align__(256) __half g_h1[2][BATCH * HID];
__device__ __align__(256) float g_h1f[BATCH * HID];
__device__ __align__(256) float g_pg[128 * 512 * 16];   // partial gates, 4MB
__device__ __align__(256) float g_c0[BATCH * HID];
__device__ __align__(256) float g_c1[BATCH * HID];
__device__ __align__(256) float g_b0[G4];
__device__ __align__(256) float g_b1[G4];

// ---------------- helpers ----------------
__device__ __forceinline__ int swz(int k, int r) {
    return (((k >> 3) ^ (r & 7)) << 3) | (k & 7);
}
__device__ __forceinline__ uint32_t smem_u32(const void* p) {
    uint32_t a;
    asm("{ .reg .u64 t; cvta.to.shared.u64 t, %1; cvt.u32.u64 %0, t; }" : "=r"(a) : "l"(p));
    return a;
}
__device__ __forceinline__ void cpbulk(uint32_t dst, const void* src, uint32_t bytes,
                                       uint32_t mbar) {
    asm volatile(
        "cp.async.bulk.shared::cluster.global.mbarrier::complete_tx::bytes "
        "[%0], [%1], %2, [%3];"
        :: "r"(dst), "l"(src), "r"(bytes), "r"(mbar) : "memory");
}
#define FENCE_ASYNC() asm volatile("fence.proxy.async.shared::cta;" ::: "memory")
#define MBAR_INIT(a, n) asm volatile("mbarrier.init.shared.b64 [%0], %1;" :: "r"(a), "r"(n) : "memory")
#define MBAR_EXPECT_TX(a, tx) asm volatile("mbarrier.arrive.expect_tx.shared.b64 _, [%0], %1;" :: "r"(a), "r"(tx) : "memory")
#define MBAR_ARRIVE(a) asm volatile("mbarrier.arrive.shared.b64 _, [%0];" :: "r"(a) : "memory")

__device__ __forceinline__ void mbar_wait(uint32_t mbar, uint32_t parity) {
    asm volatile(
        "{\n\t.reg .pred P1;\n\t"
        "WL_%=:\n\t"
        "mbarrier.try_wait.parity.acquire.cta.shared::cta.b64 P1, [%0], %1, 0x989680;\n\t"
        "@P1 bra.uni WD_%=;\n\t"
        "bra.uni WL_%=;\n\t"
        "WD_%=:\n\t}"
        :: "r"(mbar), "r"(parity) : "memory");
}
__device__ __forceinline__ void ldsm4(uint32_t* r, uint32_t addr) {
    asm volatile("ldmatrix.sync.aligned.m8n8.x4.shared.b16 {%0,%1,%2,%3}, [%4];"
                 : "=r"(r[0]), "=r"(r[1]), "=r"(r[2]), "=r"(r[3]) : "r"(addr));
}
__device__ __forceinline__ void mma16816h(uint32_t* d, const uint32_t* a,
                                          const uint32_t* b) {
    asm volatile(
        "mma.sync.aligned.m16n8k16.row.col.f16.f16.f16.f16 "
        "{%0,%1}, {%2,%3,%4,%5}, {%6,%7}, {%0,%1};"
        : "+r"(d[0]), "+r"(d[1])
        : "r"(a[0]), "r"(a[1]), "r"(a[2]), "r"(a[3]), "r"(b[0]), "r"(b[1]));
}
__device__ __forceinline__ float sigf(float x) { return 1.0f / (1.0f + __expf(-x)); }

// ---------------- prep kernels ----------------
__global__ void prep_w0(const float* __restrict__ wih, const float* __restrict__ whh) {
    int idx = blockIdx.x * blockDim.x + threadIdx.x;
    if (idx >= G4 * (64 + HID)) return;
    int n = idx / (64 + HID), k = idx - n * (64 + HID);
    int row = (n & 3) * HID + (n >> 2);
    float v;
    if (k < 64) v = (k < 32) ? wih[row * 32 + k] : 0.0f;
    else        v = whh[row * HID + (k - 64)];
    int r = n & 127;
    size_t dst = ((size_t)((n >> 7) * NCH0 + (k >> 6)) * 128 + r) * 64 + swz(k & 63, r);
    g_w0[dst] = __float2half(v);
}
__global__ void prep_w1(const float* __restrict__ wih, const float* __restrict__ whh) {
    int idx = blockIdx.x * blockDim.x + threadIdx.x;
    if (idx >= G4 * 1024) return;
    int n = idx >> 10, k = idx & 1023;
    int row = (n & 3) * HID + (n >> 2);
    float v = (k < HID) ? wih[row * HID + k] : whh[row * HID + (k - HID)];
    int r = n & 127;
    size_t dst = ((size_t)((n >> 7) * NCH1 + (k >> 6)) * 128 + r) * 64 + swz(k & 63, r);
    g_w1[dst] = __float2half(v);
}
__global__ void prep_misc(const float* __restrict__ x,
                          const float* __restrict__ h0in, const float* __restrict__ c0in,
                          const float* __restrict__ bi0, const float* __restrict__ bh0,
                          const float* __restrict__ bi1, const float* __restrict__ bh1) {
    int idx = blockIdx.x * blockDim.x + threadIdx.x;
    if (idx < SEQ * BATCH * 64) {   // xpad
        int k = idx & 63, b = (idx >> 6) & 511, t = idx >> 15;
        float v = (k < 32) ? x[((size_t)t * BATCH + b) * 32 + k] : 0.0f;
        g_xp[((size_t)t * BATCH + b) * 64 + swz(k, b)] = __float2half(v);
    }
    if (idx < BATCH * 64) g_ip[idx] = __float2half(0.0f);
    if (idx < G4) {
        int row = (idx & 3) * HID + (idx >> 2);
        g_b0[idx] = bi0[row] + bh0[row];
        g_b1[idx] = bi1[row] + bh1[row];
    }
    if (idx < BATCH * HID) {
        int b = idx >> 9, j = idx & (HID - 1);
        size_t dst = ((size_t)(j >> 6) * BATCH + b) * 64 + swz(j & 63, b);
        g_h0[0][dst] = __float2half(h0in[j]);
        g_h1[0][dst] = __float2half(h0in[HID + j]);
        g_c0[idx] = c0in[j];
        g_c1[idx] = c0in[HID + j];
    }
}

// ---------------- cell parameters ----------------
struct CellP {
    const __half* slab0;    // chunk0 A slab (xp row / g_ip) or null
    const __half* a1;       // h chunks (local 0..7 after slab0)
    const __half* a2;       // h chunks local 8..15 (encoder l1)
    const __half* wt;       // weight tile base
    int nch, woff, wstride;
    const float* bias;
    float* cbuf;
    __half* hOut;
    float* hOutF;
    float* pgOut;           // l1a: write raw partial gates, skip LSTM epilogue
    const float* pgIn;      // l1b: add partial gates before epilogue
};

// ------------ fused LSTM cell (16 warps, 2-slot ring, 2 CTAs/SM) ---------------
__global__ __launch_bounds__(THREADS, 2)
void lstm_cell(CellP A0, CellP A1)
{
    const CellP P = blockIdx.z ? A1 : A0;
    extern __shared__ char smem_raw[];
    const uint32_t sb = smem_u32(smem_raw);
    const uint32_t mb = sb + MBAR_OFF;          // full[0..1] @ +0,8 ; free[0..1] @ +16,24
    const int tid = threadIdx.x;
    const int l = tid & 31, w = tid >> 5;
    const int wm = w & 3;
    const int wn = w >> 2;
    const int n0 = blockIdx.x * 128;
    const int m0 = blockIdx.y * 64;
    const int nch = P.nch;
    const int nslots = (nch + 1) >> 1;

    if (tid == 0) {
#pragma unroll
        for (int s = 0; s < 2; ++s) MBAR_INIT(mb + s * 8, 1);       // full (tx)
#pragma unroll
        for (int s = 0; s < 2; ++s) MBAR_INIT(mb + 16 + s * 8, 16); // free (16 warps)
    }
    __syncthreads();

    const char* wbase = (const char*)P.wt +
        ((size_t)blockIdx.x * P.wstride + P.woff) * B_TILE_B;

    auto srcA = [&](int c) -> const char* {
        if (c == 0 && P.slab0 != nullptr)
            return (const char*)P.slab0 + (size_t)m0 * 128;
        int s1 = c - (P.slab0 != nullptr ? 1 : 0);
        const __half* base = (s1 < 8) ? P.a1 : P.a2;
        if (s1 >= 8) s1 -= 8;
        return (const char*)base + (size_t)s1 * CHSLAB + (size_t)m0 * 128;
    };

    auto issue = [&](int k) {
        if (k >= 2)   // ring reuse: wait until all 16 warps consumed slot k-2
            mbar_wait(mb + 16 + (uint32_t)(k & 1) * 8, (uint32_t)((k / 2 - 1) & 1));
        const int c0 = 2 * k;
        const bool has2 = (c0 + 1 < nch);
        const uint32_t st = sb + (uint32_t)(k & 1) * SLOT_B;
        const uint32_t m = mb + (uint32_t)(k & 1) * 8;
        FENCE_ASYNC();
        MBAR_EXPECT_TX(m, (has2 ? 2u : 1u) * (A_TILE_B + B_TILE_B));
        cpbulk(st, srcA(c0), A_TILE_B, m);
        if (has2) cpbulk(st + A_TILE_B, srcA(c0 + 1), A_TILE_B, m);
        cpbulk(st + 2 * A_TILE_B, wbase + (size_t)c0 * B_TILE_B,
               (has2 ? 2u : 1u) * B_TILE_B, m);
    };

    if (tid == 0) {
        issue(0);
        if (nslots > 1) issue(1);
    }

    float acc[4][4];
#pragma unroll
    for (int nt = 0; nt < 4; ++nt)
#pragma unroll
        for (int i = 0; i < 4; ++i) acc[nt][i] = 0.0f;

    const uint32_t aRow = (uint32_t)(wm * 16 + (l & 15));
    const uint32_t aQl = (uint32_t)(l >> 4);
    const uint32_t bRowB = (uint32_t)(wn * 32 + (l & 7) + ((l >> 4) & 1) * 8);
    const uint32_t bQl = (uint32_t)((l >> 3) & 1);

    auto chunk_mma = [&](uint32_t aB, uint32_t bB) {
        uint32_t d16[4][2];
#pragma unroll
        for (int nt = 0; nt < 4; ++nt) { d16[nt][0] = 0u; d16[nt][1] = 0u; }
#pragma unroll
        for (int ks = 0; ks < 4; ++ks) {
            const uint32_t qa = aQl + ks * 2;
            uint32_t a[4];
            ldsm4(a, aB + aRow * 128 + ((qa ^ (aRow & 7)) << 4));
            uint32_t b[4][2];
#pragma unroll
            for (int ntp = 0; ntp < 2; ++ntp) {
                const uint32_t br = bRowB + ntp * 16;
                const uint32_t qb = bQl + ks * 2;
                uint32_t r4[4];
                ldsm4(r4, bB + br * 128 + ((qb ^ (br & 7)) << 4));
                b[ntp * 2][0] = r4[0]; b[ntp * 2][1] = r4[1];
                b[ntp * 2 + 1][0] = r4[2]; b[ntp * 2 + 1][1] = r4[3];
            }
#pragma unroll
            for (int nt = 0; nt < 4; ++nt)
                mma16816h(d16[nt], a, b[nt]);
        }
#pragma unroll
        for (int nt = 0; nt < 4; ++nt) {
            float2 p0 = __half22float2(*(const __half2*)&d16[nt][0]);
            float2 p1 = __half22float2(*(const __half2*)&d16[nt][1]);
            acc[nt][0] += p0.x; acc[nt][1] += p0.y;
            acc[nt][2] += p1.x; acc[nt][3] += p1.y;
        }
    };

    for (int slot = 0; slot < nslots; ++slot) {
        mbar_wait(mb + (uint32_t)(slot & 1) * 8, (uint32_t)((slot / 2) & 1));
        const uint32_t stage = sb + (uint32_t)(slot & 1) * SLOT_B;
        chunk_mma(stage, stage + 2 * A_TILE_B);
        if (2 * slot + 1 < nch)
            chunk_mma(stage + A_TILE_B, stage + 2 * A_TILE_B + B_TILE_B);
        if (l == 0) MBAR_ARRIVE(mb + 16 + (uint32_t)(slot & 1) * 8);
        if (tid == 0 && slot + 2 < nslots) issue(slot + 2);
    }

    // ---- partial-gate write path (l1a) ----
    const size_t pgbase =
        (((size_t)blockIdx.x * 8 + blockIdx.y) * THREADS + tid) * 16;
    if (P.pgOut != nullptr) {
#pragma unroll
        for (int nt = 0; nt < 4; ++nt)
            *(float4*)(P.pgOut + pgbase + nt * 4) =
                make_float4(acc[nt][0], acc[nt][1], acc[nt][2], acc[nt][3]);
        return;
    }

    // ---- epilogue ----
    const bool odd = (l & 1) != 0;
#pragma unroll
    for (int nt = 0; nt < 4; ++nt) {
        float* cc = acc[nt];
        if (P.pgIn != nullptr) {
            float4 pg = *(const float4*)(P.pgIn + pgbase + nt * 4);
            cc[0] += pg.x; cc[1] += pg.y; cc[2] += pg.z; cc[3] += pg.w;
        }
        float send1 = odd ? cc[0] : cc[2];
        float send2 = odd ? cc[1] : cc[3];
        float r1 = __shfl_xor_sync(0xffffffffu, send1, 1);
        float r2 = __shfl_xor_sync(0xffffffffu, send2, 1);
        float gi, gf, gg, go;
        if (!odd) { gi = cc[0]; gf = cc[1]; gg = r1; go = r2; }
        else      { gi = r1;    gf = r2;    gg = cc[2]; go = cc[3]; }

        const int j = ((n0 + wn * 32 + nt * 8) >> 2) + ((l & 3) >> 1);
        const float4 b4 = *(const float4*)(P.bias + 4 * j);
        gi += b4.x; gf += b4.y; gg += b4.z; go += b4.w;

        const int bglob = m0 + wm * 16 + (l >> 2) + (odd ? 8 : 0);
        const int ix = bglob * HID + j;
        float cp = P.cbuf[ix];
        float cn = sigf(gf) * cp + sigf(gi) * tanhf(gg);
        float hn = sigf(go) * tanhf(cn);
        P.cbuf[ix] = cn;
        P.hOut[((size_t)(j >> 6) * BATCH + bglob) * 64 + swz(j & 63, bglob)] =
            __float2half(hn);
        if (P.hOutF != nullptr) P.hOutF[ix] = hn;
    }
}

// ---------------- FC head (+ next decode-input packing, swizzled) ----------------
__global__ void fc_head(const float* __restrict__ h1f,
                        const float* __restrict__ fcw, const float* __restrict__ fcb,
                        float* __restrict__ outp, const float* __restrict__ tf) {
    int idx = blockIdx.x * blockDim.x + threadIdx.x;   // 4096 = B*OUT
    int b = idx >> 3, o = idx & 7;
    const float4* h4 = (const float4*)(h1f + (size_t)b * HID);
    const float4* w4 = (const float4*)(fcw + (size_t)o * HID);
    float s = fcb[o];
#pragma unroll 4
    for (int j = 0; j < HID / 4; ++j) {
        float4 a = h4[j], wv = w4[j];
        s += a.x * wv.x + a.y * wv.y + a.z * wv.z + a.w * wv.w;
    }
    outp[b * OUT_DIM + o] = s;
    if (tf != nullptr) {
        g_ip[(size_t)b * 64 + swz(o, b)] = __float2half(s);
#pragma unroll
        for (int m = 0; m < 3; ++m) {
            int kk = 8 + o * 3 + m;
            g_ip[(size_t)b * 64 + swz(kk, b)] =
                __float2half(tf[(size_t)b * TF_DIM + o * 3 + m]);
        }
    }
}

// ---------------- host orchestration ----------------
extern "C" void kernel_launch(void* const* d_in, const int* in_sizes, int n_in,
                              void* d_out, int out_size) {
    const float* x     = (const float*)d_in[0];
    const float* ft    = (const float*)d_in[1];
    const float* h0in  = (const float*)d_in[2];
    const float* c0in  = (const float*)d_in[3];
    const float* w_ih0 = (const float*)d_in[4];
    const float* w_hh0 = (const float*)d_in[5];
    const float* b_ih0 = (const float*)d_in[6];
    const float* b_hh0 = (const float*)d_in[7];
    const float* w_ih1 = (const float*)d_in[8];
    const float* w_hh1 = (const float*)d_in[9];
    const float* b_ih1 = (const float*)d_in[10];
    const float* b_hh1 = (const float*)d_in[11];
    const float* fcw   = (const float*)d_in[12];
    const float* fcb   = (const float*)d_in[13];
    float* out = (float*)d_out;

    cudaFuncSetAttribute(lstm_cell, cudaFuncAttributeMaxDynamicSharedMemorySize, SMEM_B);

    __half *w0p, *w1p, *xp, *ip, *h0p, *h1p;
    float *h1fp, *pgp, *c0p, *c1p, *b0p, *b1p;
    cudaGetSymbolAddress((void**)&w0p, g_w0);
    cudaGetSymbolAddress((void**)&w1p, g_w1);
    cudaGetSymbolAddress((void**)&xp, g_xp);
    cudaGetSymbolAddress((void**)&ip, g_ip);
    cudaGetSymbolAddress((void**)&h0p, g_h0);
    cudaGetSymbolAddress((void**)&h1p, g_h1);
    cudaGetSymbolAddress((void**)&h1fp, g_h1f);
    cudaGetSymbolAddress((void**)&pgp, g_pg);
    cudaGetSymbolAddress((void**)&c0p, g_c0);
    cudaGetSymbolAddress((void**)&c1p, g_c1);
    cudaGetSymbolAddress((void**)&b0p, g_b0);
    cudaGetSymbolAddress((void**)&b1p, g_b1);

    prep_w0<<<(G4 * (64 + HID) + 255) / 256, 256>>>(w_ih0, w_hh0);
    prep_w1<<<(G4 * 1024 + 255) / 256, 256>>>(w_ih1, w_hh1);
    prep_misc<<<(SEQ * BATCH * 64 + 255) / 256, 256>>>(x, h0in, c0in,
                                                       b_ih0, b_hh0, b_ih1, b_hh1);

    const int SN = BATCH * HID;
    CellP Z = {};

    auto mk_l0 = [&](int s, const __half* slab) {
        CellP a = {};
        a.slab0 = slab;
        a.a1 = h0p + (size_t)(s & 1) * SN;
        a.wt = w0p; a.nch = NCH0; a.woff = 0; a.wstride = NCH0;
        a.bias = b0p; a.cbuf = c0p;
        a.hOut = h0p + (size_t)((s + 1) & 1) * SN;
        return a;
    };
    auto mk_l1full = [&](int s, bool wf) {
        CellP a = {};
        a.a1 = h0p + (size_t)((s + 1) & 1) * SN;
        a.a2 = h1p + (size_t)(s & 1) * SN;
        a.wt = w1p; a.nch = NCH1; a.woff = 0; a.wstride = NCH1;
        a.bias = b1p; a.cbuf = c1p;
        a.hOut = h1p + (size_t)((s + 1) & 1) * SN;
        a.hOutF = wf ? h1fp : nullptr;
        return a;
    };
    auto mk_l1a = [&](int s) {   // h1_old half -> partial gates
        CellP a = {};
        a.a1 = h1p + (size_t)(s & 1) * SN;
        a.wt = w1p; a.nch = 8; a.woff = 8; a.wstride = NCH1;
        a.pgOut = pgp;
        return a;
    };
    auto mk_l1b = [&](int s) {   // h0_new half + partial add
        CellP a = {};
        a.a1 = h0p + (size_t)((s + 1) & 1) * SN;
        a.wt = w1p; a.nch = 8; a.woff = 0; a.wstride = NCH1;
        a.pgIn = pgp;
        a.bias = b1p; a.cbuf = c1p;
        a.hOut = h1p + (size_t)((s + 1) & 1) * SN;
        a.hOutF = h1fp;
        return a;
    };

    const dim3 gridS(16, 8, 1), gridC(16, 8, 2);

    // encoder: pair l1(t) with independent l0(t+1) — now single co-resident wave
    lstm_cell<<<gridS, THREADS, SMEM_B>>>(mk_l0(0, xp), Z);
    for (int t = 0; t < SEQ - 1; ++t)
        lstm_cell<<<gridC, THREADS, SMEM_B>>>(mk_l1full(t, false),
                                              mk_l0(t + 1, xp + (size_t)(t + 1) * BATCH * 64));
    lstm_cell<<<gridS, THREADS, SMEM_B>>>(mk_l1full(SEQ - 1, true), Z);

    fc_head<<<16, 256>>>(h1fp, fcw, fcb, out, ft);

    // autoregressive decode: pair l0dec(d) with l1a(d); l1b finishes
    for (int d = 0; d < FUT - 1; ++d) {
        const int s = SEQ + d;
        lstm_cell<<<gridC, THREADS, SMEM_B>>>(mk_l0(s, ip), mk_l1a(s));
        lstm_cell<<<gridS, THREADS, SMEM_B>>>(mk_l1b(s), Z);
        fc_head<<<16, 256>>>(h1fp, fcw, fcb,
                             out + (size_t)(d + 1) * BATCH * OUT_DIM,
                             (d + 1 < FUT - 1) ? (ft + (size_t)(d + 1) * BATCH * TF_DIM)
                                               : nullptr);
    }
}